// round 2
// baseline (speedup 1.0000x reference)
#include <cuda_runtime.h>

#define N_NODES 50000
#define N_EDGES 800000
#define F_IN 128
#define HIDDEN 128
#define N_CLASSES 10
#define N_GRAPHS 256

// -------- scratch (static device globals; no dynamic alloc allowed) --------
__device__ float g_deg[N_NODES];
__device__ float g_gcnt[N_GRAPHS];
__device__ float g_pool[N_GRAPHS * N_CLASSES];
__device__ __align__(16) float g_A[N_NODES * HIDDEN];
__device__ __align__(16) float g_B[N_NODES * HIDDEN];
__device__ __align__(16) float g_S[N_NODES * HIDDEN];
__device__ __align__(16) float g_H[N_NODES * HIDDEN];
__device__ float g_A3[N_NODES * N_CLASSES];
__device__ float g_B3[N_NODES * N_CLASSES];
__device__ float g_S3[N_NODES * N_CLASSES];

// -------- zeroing --------
__global__ void zero_common_kernel() {
    int i = blockIdx.x * blockDim.x + threadIdx.x;
    if (i < N_NODES) g_deg[i] = 0.f;
    if (i < N_GRAPHS) g_gcnt[i] = 0.f;
    if (i < N_GRAPHS * N_CLASSES) g_pool[i] = 0.f;
}

__global__ void zero_S_kernel() {  // zero g_S as float4
    int i = blockIdx.x * blockDim.x + threadIdx.x;
    if (i < N_NODES * (HIDDEN / 4))
        ((float4*)g_S)[i] = make_float4(0.f, 0.f, 0.f, 0.f);
}

__global__ void zero_S3_kernel() {
    int i = blockIdx.x * blockDim.x + threadIdx.x;
    if (i < N_NODES * N_CLASSES) g_S3[i] = 0.f;
}

// -------- degree / graph counts (edge_index/batch are INT32: jax x64 off) ----
__global__ void degree_kernel(const int* __restrict__ ei) {
    int e = blockIdx.x * blockDim.x + threadIdx.x;
    if (e < N_EDGES) {
        int dst = ei[N_EDGES + e];
        atomicAdd(&g_deg[dst], 1.0f);
    }
}

__global__ void gcnt_kernel(const int* __restrict__ batch) {
    int i = blockIdx.x * blockDim.x + threadIdx.x;
    if (i < N_NODES) atomicAdd(&g_gcnt[batch[i]], 1.0f);
}

// -------- dual GEMM: A = X@Wl, B = X@Wr  (Din=128, Dout=128 each) --------
// Block: 256 threads, 32 rows. W (128x256 combined) staged in smem (128KB),
// X tile 32x132 (padded) in smem. Each thread: 1 row x 32 cols register tile.
__global__ __launch_bounds__(256) void gemm_dual128(
    const float* __restrict__ X, const float* __restrict__ Wl,
    const float* __restrict__ Wr, float* __restrict__ A, float* __restrict__ B) {
    extern __shared__ float sm[];
    float* Ws = sm;               // [128][256]
    float* Xs = sm + 128 * 256;   // [32][132] padded
    const int tid = threadIdx.x;

    // stage W: Ws[k][0:128] = Wl row k, Ws[k][128:256] = Wr row k
    for (int i = tid; i < 128 * 128 / 4; i += 256) {
        int k = (i * 4) >> 7;
        int c = (i * 4) & 127;
        float4 wl = ((const float4*)Wl)[i];
        float4 wr = ((const float4*)Wr)[i];
        *((float4*)&Ws[k * 256 + c]) = wl;
        *((float4*)&Ws[k * 256 + 128 + c]) = wr;
    }
    const int row0 = blockIdx.x * 32;
    for (int i = tid; i < 32 * 128 / 4; i += 256) {
        int r = (i * 4) >> 7;
        int c = (i * 4) & 127;
        int gr = row0 + r;
        float4 v = (gr < N_NODES) ? ((const float4*)X)[gr * 32 + (c >> 2)]
                                  : make_float4(0.f, 0.f, 0.f, 0.f);
        *((float4*)&Xs[r * 132 + c]) = v;
    }
    __syncthreads();

    const int r = tid >> 3;
    const int colbase = (tid & 7) * 32;
    float acc[32];
#pragma unroll
    for (int j = 0; j < 32; j++) acc[j] = 0.f;

#pragma unroll 4
    for (int k = 0; k < 128; k++) {
        float xv = Xs[r * 132 + k];
#pragma unroll
        for (int j = 0; j < 8; j++) {
            float4 w = *((const float4*)&Ws[k * 256 + colbase + j * 4]);
            acc[j * 4 + 0] += xv * w.x;
            acc[j * 4 + 1] += xv * w.y;
            acc[j * 4 + 2] += xv * w.z;
            acc[j * 4 + 3] += xv * w.w;
        }
    }

    const int gr = row0 + r;
    if (gr < N_NODES) {
        float* dstp = (colbase < 128) ? (A + gr * 128 + colbase)
                                      : (B + gr * 128 + (colbase - 128));
#pragma unroll
        for (int j = 0; j < 8; j++)
            ((float4*)dstp)[j] =
                make_float4(acc[j * 4], acc[j * 4 + 1], acc[j * 4 + 2], acc[j * 4 + 3]);
    }
}

// -------- edge scatter-add, 128-dim: 32 threads/edge, float4 red --------
__global__ __launch_bounds__(256) void scatter128(
    const int* __restrict__ ei, const float* __restrict__ A,
    float* __restrict__ S) {
    int gid = blockIdx.x * blockDim.x + threadIdx.x;
    int e = gid >> 5;
    int lane = gid & 31;
    if (e >= N_EDGES) return;
    int src = ei[e];
    int dst = ei[N_EDGES + e];
    float4 v = ((const float4*)A)[src * 32 + lane];
    float* p = S + (size_t)dst * 128 + lane * 4;
    asm volatile("red.global.add.v4.f32 [%0], {%1,%2,%3,%4};"
                 :: "l"(p), "f"(v.x), "f"(v.y), "f"(v.z), "f"(v.w)
                 : "memory");
}

// -------- finalize: H = S/max(deg,1) + B + bias --------
__global__ void finalize128(const float* __restrict__ S, const float* __restrict__ B,
                            const float* __restrict__ bias, float* __restrict__ H) {
    int gid = blockIdx.x * blockDim.x + threadIdx.x;  // over N*32 float4s
    if (gid >= N_NODES * 32) return;
    int row = gid >> 5;
    int c4 = gid & 31;
    float d = g_deg[row];
    float inv = 1.0f / (d > 1.0f ? d : 1.0f);
    float4 s = ((const float4*)S)[gid];
    float4 b = ((const float4*)B)[gid];
    float4 bi = ((const float4*)bias)[c4];
    float4 h;
    h.x = s.x * inv + b.x + bi.x;
    h.y = s.y * inv + b.y + bi.y;
    h.z = s.z * inv + b.z + bi.z;
    h.w = s.w * inv + b.w + bi.w;
    ((float4*)H)[gid] = h;
}

// -------- layer-3 dual GEMM: Dout=10, warp per row --------
__global__ __launch_bounds__(256) void gemm_dual10(
    const float* __restrict__ X, const float* __restrict__ Wl,
    const float* __restrict__ Wr, float* __restrict__ A, float* __restrict__ B) {
    int warp = (blockIdx.x * blockDim.x + threadIdx.x) >> 5;
    int lane = threadIdx.x & 31;
    if (warp >= N_NODES) return;
    float xv[4];
#pragma unroll
    for (int i = 0; i < 4; i++) xv[i] = X[warp * 128 + lane + 32 * i];
#pragma unroll
    for (int c = 0; c < N_CLASSES; c++) {
        float a = 0.f, b = 0.f;
#pragma unroll
        for (int i = 0; i < 4; i++) {
            int k = lane + 32 * i;
            a += xv[i] * Wl[k * N_CLASSES + c];
            b += xv[i] * Wr[k * N_CLASSES + c];
        }
#pragma unroll
        for (int off = 16; off > 0; off >>= 1) {
            a += __shfl_xor_sync(0xFFFFFFFFu, a, off);
            b += __shfl_xor_sync(0xFFFFFFFFu, b, off);
        }
        if (lane == 0) {
            A[warp * N_CLASSES + c] = a;
            B[warp * N_CLASSES + c] = b;
        }
    }
}

// -------- edge scatter-add, 10-dim: 16 threads/edge (10 active) --------
__global__ __launch_bounds__(256) void scatter10(
    const int* __restrict__ ei, const float* __restrict__ A,
    float* __restrict__ S) {
    int gid = blockIdx.x * blockDim.x + threadIdx.x;
    int e = gid >> 4;
    int lane = gid & 15;
    if (e >= N_EDGES || lane >= N_CLASSES) return;
    int src = ei[e];
    int dst = ei[N_EDGES + e];
    atomicAdd(&S[dst * N_CLASSES + lane], A[src * N_CLASSES + lane]);
}

// -------- finalize layer 3 + global mean pool accumulation --------
__global__ void finalize10_pool(const float* __restrict__ S3, const float* __restrict__ B3,
                                const float* __restrict__ bl3,
                                const int* __restrict__ batch) {
    int gid = blockIdx.x * blockDim.x + threadIdx.x;
    if (gid >= N_NODES * N_CLASSES) return;
    int row = gid / N_CLASSES;
    int c = gid - row * N_CLASSES;
    float d = g_deg[row];
    float inv = 1.0f / (d > 1.0f ? d : 1.0f);
    float h = S3[gid] * inv + B3[gid] + bl3[c];
    atomicAdd(&g_pool[batch[row] * N_CLASSES + c], h);
}

// -------- pooled mean + log_softmax --------
__global__ void final_out_kernel(float* __restrict__ out) {
    int g = threadIdx.x;  // 256 graphs, 1 block
    if (g >= N_GRAPHS) return;
    float cnt = g_gcnt[g];
    float inv = 1.0f / (cnt > 1.0f ? cnt : 1.0f);
    float v[N_CLASSES];
    float mx = -1e30f;
#pragma unroll
    for (int c = 0; c < N_CLASSES; c++) {
        v[c] = g_pool[g * N_CLASSES + c] * inv;
        mx = v[c] > mx ? v[c] : mx;
    }
    float s = 0.f;
#pragma unroll
    for (int c = 0; c < N_CLASSES; c++) s += expf(v[c] - mx);
    float ls = logf(s);
#pragma unroll
    for (int c = 0; c < N_CLASSES; c++) out[g * N_CLASSES + c] = v[c] - mx - ls;
}

// -------- host launch --------
extern "C" void kernel_launch(void* const* d_in, const int* in_sizes, int n_in,
                              void* d_out, int out_size) {
    const float* x = (const float*)d_in[0];
    const int* ei = (const int*)d_in[1];     // int32 (jax x64 disabled)
    const int* batch = (const int*)d_in[2];  // int32
    const float* Wl1 = (const float*)d_in[3];
    const float* bl1 = (const float*)d_in[4];
    const float* Wr1 = (const float*)d_in[5];
    const float* Wl2 = (const float*)d_in[6];
    const float* bl2 = (const float*)d_in[7];
    const float* Wr2 = (const float*)d_in[8];
    const float* Wl3 = (const float*)d_in[9];
    const float* bl3 = (const float*)d_in[10];
    const float* Wr3 = (const float*)d_in[11];
    float* out = (float*)d_out;

    float *A, *B, *S, *H, *A3, *B3, *S3;
    cudaGetSymbolAddress((void**)&A, g_A);
    cudaGetSymbolAddress((void**)&B, g_B);
    cudaGetSymbolAddress((void**)&S, g_S);
    cudaGetSymbolAddress((void**)&H, g_H);
    cudaGetSymbolAddress((void**)&A3, g_A3);
    cudaGetSymbolAddress((void**)&B3, g_B3);
    cudaGetSymbolAddress((void**)&S3, g_S3);

    const int SMEM = (128 * 256 + 32 * 132) * 4;
    static bool attr_done = false;
    if (!attr_done) {
        cudaFuncSetAttribute(gemm_dual128, cudaFuncAttributeMaxDynamicSharedMemorySize, SMEM);
        attr_done = true;
    }

    const int gemm_grid = (N_NODES + 31) / 32;
    const int scat_grid = (N_EDGES * 32 + 255) / 256;
    const int fin_grid = (N_NODES * 32 + 255) / 256;
    const int scat10_grid = (N_EDGES * 16 + 255) / 256;
    const int fin10_grid = (N_NODES * N_CLASSES + 255) / 256;

    zero_common_kernel<<<(N_NODES + 255) / 256, 256>>>();
    degree_kernel<<<(N_EDGES + 255) / 256, 256>>>(ei);
    gcnt_kernel<<<(N_NODES + 255) / 256, 256>>>(batch);

    // ---- layer 1 ----
    zero_S_kernel<<<(N_NODES * 32 + 255) / 256, 256>>>();
    gemm_dual128<<<gemm_grid, 256, SMEM>>>(x, Wl1, Wr1, A, B);
    scatter128<<<scat_grid, 256>>>(ei, A, S);
    finalize128<<<fin_grid, 256>>>(S, B, bl1, H);

    // ---- layer 2 ----
    zero_S_kernel<<<(N_NODES * 32 + 255) / 256, 256>>>();
    gemm_dual128<<<gemm_grid, 256, SMEM>>>(H, Wl2, Wr2, A, B);
    scatter128<<<scat_grid, 256>>>(ei, A, S);
    finalize128<<<fin_grid, 256>>>(S, B, bl2, H);

    // ---- layer 3 (10-dim aggregation thanks to linearity) ----
    zero_S3_kernel<<<(N_NODES * N_CLASSES + 255) / 256, 256>>>();
    gemm_dual10<<<(N_NODES * 32 + 255) / 256, 256>>>(H, Wl3, Wr3, A3, B3);
    scatter10<<<scat10_grid, 256>>>(ei, A3, S3);
    finalize10_pool<<<fin10_grid, 256>>>(S3, B3, bl3, batch);

    final_out_kernel<<<1, 256>>>(out);
}

// round 3
// speedup vs baseline: 6.4877x; 6.4877x over previous
#include <cuda_runtime.h>

#define N_NODES 50000
#define N_EDGES 800000
#define F_IN 128
#define HIDDEN 128
#define N_CLASSES 10
#define N_GRAPHS 256

// -------- scratch (static device globals) --------
__device__ int g_degi[N_NODES];
__device__ int g_off[N_NODES + 1];
__device__ int g_cur[N_NODES];
__device__ int g_csr_src[N_EDGES];
__device__ float g_gcnt[N_GRAPHS];
__device__ float g_pool[N_GRAPHS * N_CLASSES];
__device__ __align__(16) float g_A[N_NODES * HIDDEN];
__device__ __align__(16) float g_B[N_NODES * HIDDEN];
__device__ __align__(16) float g_H[N_NODES * HIDDEN];
__device__ float g_A3[N_NODES * N_CLASSES];
__device__ float g_B3[N_NODES * N_CLASSES];

// -------- zero + counts --------
__global__ void zero_misc_kernel() {
    int i = blockIdx.x * blockDim.x + threadIdx.x;
    if (i < N_NODES) g_degi[i] = 0;
    if (i < N_GRAPHS) g_gcnt[i] = 0.f;
    if (i < N_GRAPHS * N_CLASSES) g_pool[i] = 0.f;
}

__global__ void count_deg_kernel(const int* __restrict__ ei) {
    int e = blockIdx.x * blockDim.x + threadIdx.x;
    if (e < N_EDGES) atomicAdd(&g_degi[ei[N_EDGES + e]], 1);
}

__global__ void gcnt_kernel(const int* __restrict__ batch) {
    int i = blockIdx.x * blockDim.x + threadIdx.x;
    if (i < N_NODES) atomicAdd(&g_gcnt[batch[i]], 1.0f);
}

// -------- single-block exclusive scan over 50K degrees --------
__global__ __launch_bounds__(1024) void scan_kernel() {
    __shared__ int part[1024];
    const int t = threadIdx.x;
    const int CH = (N_NODES + 1023) / 1024;  // 49
    int beg = t * CH;
    int end = beg + CH < N_NODES ? beg + CH : N_NODES;
    int s = 0;
    for (int i = beg; i < end; i++) s += g_degi[i];
    part[t] = s;
    __syncthreads();
    // Hillis-Steele inclusive scan
    for (int off = 1; off < 1024; off <<= 1) {
        int v = part[t];
        int add = (t >= off) ? part[t - off] : 0;
        __syncthreads();
        part[t] = v + add;
        __syncthreads();
    }
    int run = part[t] - s;  // exclusive prefix
    for (int i = beg; i < end; i++) {
        g_off[i] = run;
        g_cur[i] = run;
        run += g_degi[i];
    }
    if (t == 1023) g_off[N_NODES] = run;
}

__global__ void fill_csr_kernel(const int* __restrict__ ei) {
    int e = blockIdx.x * blockDim.x + threadIdx.x;
    if (e >= N_EDGES) return;
    int src = ei[e];
    int dst = ei[N_EDGES + e];
    int slot = atomicAdd(&g_cur[dst], 1);
    g_csr_src[slot] = src;
}

// -------- dual GEMM: A = X@Wl, B = X@Wr (Din=128, Dout=128 each) --------
// 256 threads, 64 rows x 256 cols per block, 8x8 register micro-tile.
// W combined in smem [128][256] (128KB), X tile [64][128] (32KB).
__global__ __launch_bounds__(256) void gemm_dual128(
    const float* __restrict__ X, const float* __restrict__ Wl,
    const float* __restrict__ Wr, float* __restrict__ A, float* __restrict__ B) {
    extern __shared__ float sm[];
    float* Ws = sm;               // [128][256]
    float* Xs = sm + 128 * 256;   // [64][128]
    float4* Ws4 = (float4*)Ws;
    const int tid = threadIdx.x;

    for (int i = tid; i < 128 * 128 / 4; i += 256) {
        int k = (i * 4) >> 7;
        int c = (i * 4) & 127;
        float4 wl = ((const float4*)Wl)[i];
        float4 wr = ((const float4*)Wr)[i];
        *((float4*)&Ws[k * 256 + c]) = wl;
        *((float4*)&Ws[k * 256 + 128 + c]) = wr;
    }
    const int row0 = blockIdx.x * 64;
    for (int i = tid; i < 64 * 32; i += 256) {
        int r = i >> 5;
        int c4 = i & 31;
        int gr = row0 + r;
        float4 v = (gr < N_NODES) ? ((const float4*)X)[gr * 32 + c4]
                                  : make_float4(0.f, 0.f, 0.f, 0.f);
        *((float4*)&Xs[r * 128 + c4 * 4]) = v;
    }
    __syncthreads();

    const int tx = tid & 31;   // col group: cols tx*8 .. tx*8+7 (of 256)
    const int ty = tid >> 5;   // row group: rows ty*8 .. ty*8+7 (of 64)
    float acc[8][8];
#pragma unroll
    for (int i = 0; i < 8; i++)
#pragma unroll
        for (int j = 0; j < 8; j++) acc[i][j] = 0.f;

#pragma unroll 2
    for (int k = 0; k < 128; k++) {
        float xv[8];
#pragma unroll
        for (int i = 0; i < 8; i++) xv[i] = Xs[(ty * 8 + i) * 128 + k];
        float4 w0 = Ws4[k * 64 + tx * 2];
        float4 w1 = Ws4[k * 64 + tx * 2 + 1];
#pragma unroll
        for (int i = 0; i < 8; i++) {
            acc[i][0] += xv[i] * w0.x;
            acc[i][1] += xv[i] * w0.y;
            acc[i][2] += xv[i] * w0.z;
            acc[i][3] += xv[i] * w0.w;
            acc[i][4] += xv[i] * w1.x;
            acc[i][5] += xv[i] * w1.y;
            acc[i][6] += xv[i] * w1.z;
            acc[i][7] += xv[i] * w1.w;
        }
    }

    const int col = tx * 8;
#pragma unroll
    for (int i = 0; i < 8; i++) {
        int gr = row0 + ty * 8 + i;
        if (gr >= N_NODES) break;
        float* base = (col < 128) ? (A + gr * 128 + col) : (B + gr * 128 + col - 128);
        ((float4*)base)[0] = make_float4(acc[i][0], acc[i][1], acc[i][2], acc[i][3]);
        ((float4*)base)[1] = make_float4(acc[i][4], acc[i][5], acc[i][6], acc[i][7]);
    }
}

// -------- CSR gather + finalize: H = mean_{src in in(n)} A[src] + B[n] + bias --------
__global__ __launch_bounds__(256) void gather_fin128(
    const float* __restrict__ A, const float* __restrict__ B,
    const float* __restrict__ bias, float* __restrict__ H) {
    int warp = (blockIdx.x * blockDim.x + threadIdx.x) >> 5;
    int lane = threadIdx.x & 31;
    if (warp >= N_NODES) return;
    const int beg = g_off[warp];
    const int end = g_off[warp + 1];
    const float4* A4 = (const float4*)A;
    float4 acc = make_float4(0.f, 0.f, 0.f, 0.f);
    int j = beg;
    for (; j + 1 < end; j += 2) {
        int s0 = g_csr_src[j];
        int s1 = g_csr_src[j + 1];
        float4 v0 = A4[s0 * 32 + lane];
        float4 v1 = A4[s1 * 32 + lane];
        acc.x += v0.x + v1.x;
        acc.y += v0.y + v1.y;
        acc.z += v0.z + v1.z;
        acc.w += v0.w + v1.w;
    }
    if (j < end) {
        float4 v = A4[g_csr_src[j] * 32 + lane];
        acc.x += v.x; acc.y += v.y; acc.z += v.z; acc.w += v.w;
    }
    int deg = end - beg;
    float inv = 1.0f / (float)(deg > 1 ? deg : 1);
    float4 b = ((const float4*)B)[warp * 32 + lane];
    float4 bi = ((const float4*)bias)[lane];
    float4 h;
    h.x = acc.x * inv + b.x + bi.x;
    h.y = acc.y * inv + b.y + bi.y;
    h.z = acc.z * inv + b.z + bi.z;
    h.w = acc.w * inv + b.w + bi.w;
    ((float4*)H)[warp * 32 + lane] = h;
}

// -------- layer-3 dual GEMM: Dout=10, warp per row --------
__global__ __launch_bounds__(256) void gemm_dual10(
    const float* __restrict__ X, const float* __restrict__ Wl,
    const float* __restrict__ Wr, float* __restrict__ A, float* __restrict__ B) {
    int warp = (blockIdx.x * blockDim.x + threadIdx.x) >> 5;
    int lane = threadIdx.x & 31;
    if (warp >= N_NODES) return;
    float xv[4];
#pragma unroll
    for (int i = 0; i < 4; i++) xv[i] = X[warp * 128 + lane + 32 * i];
#pragma unroll
    for (int c = 0; c < N_CLASSES; c++) {
        float a = 0.f, b = 0.f;
#pragma unroll
        for (int i = 0; i < 4; i++) {
            int k = lane + 32 * i;
            a += xv[i] * Wl[k * N_CLASSES + c];
            b += xv[i] * Wr[k * N_CLASSES + c];
        }
#pragma unroll
        for (int off = 16; off > 0; off >>= 1) {
            a += __shfl_xor_sync(0xFFFFFFFFu, a, off);
            b += __shfl_xor_sync(0xFFFFFFFFu, b, off);
        }
        if (lane == 0) {
            A[warp * N_CLASSES + c] = a;
            B[warp * N_CLASSES + c] = b;
        }
    }
}

// -------- layer-3 gather + finalize + graph pool accumulation --------
__global__ __launch_bounds__(256) void gather10_pool(
    const float* __restrict__ A3, const float* __restrict__ B3,
    const float* __restrict__ bl3, const int* __restrict__ batch) {
    int warp = (blockIdx.x * blockDim.x + threadIdx.x) >> 5;
    int lane = threadIdx.x & 31;
    if (warp >= N_NODES || lane >= N_CLASSES) return;
    const int beg = g_off[warp];
    const int end = g_off[warp + 1];
    float acc = 0.f;
    for (int j = beg; j < end; j++)
        acc += A3[g_csr_src[j] * N_CLASSES + lane];
    int deg = end - beg;
    float inv = 1.0f / (float)(deg > 1 ? deg : 1);
    float h = acc * inv + B3[warp * N_CLASSES + lane] + bl3[lane];
    atomicAdd(&g_pool[batch[warp] * N_CLASSES + lane], h);
}

// -------- pooled mean + log_softmax --------
__global__ void final_out_kernel(float* __restrict__ out) {
    int g = threadIdx.x;
    if (g >= N_GRAPHS) return;
    float cnt = g_gcnt[g];
    float inv = 1.0f / (cnt > 1.0f ? cnt : 1.0f);
    float v[N_CLASSES];
    float mx = -1e30f;
#pragma unroll
    for (int c = 0; c < N_CLASSES; c++) {
        v[c] = g_pool[g * N_CLASSES + c] * inv;
        mx = v[c] > mx ? v[c] : mx;
    }
    float s = 0.f;
#pragma unroll
    for (int c = 0; c < N_CLASSES; c++) s += expf(v[c] - mx);
    float ls = logf(s);
#pragma unroll
    for (int c = 0; c < N_CLASSES; c++) out[g * N_CLASSES + c] = v[c] - mx - ls;
}

// -------- host launch --------
extern "C" void kernel_launch(void* const* d_in, const int* in_sizes, int n_in,
                              void* d_out, int out_size) {
    const float* x = (const float*)d_in[0];
    const int* ei = (const int*)d_in[1];
    const int* batch = (const int*)d_in[2];
    const float* Wl1 = (const float*)d_in[3];
    const float* bl1 = (const float*)d_in[4];
    const float* Wr1 = (const float*)d_in[5];
    const float* Wl2 = (const float*)d_in[6];
    const float* bl2 = (const float*)d_in[7];
    const float* Wr2 = (const float*)d_in[8];
    const float* Wl3 = (const float*)d_in[9];
    const float* bl3 = (const float*)d_in[10];
    const float* Wr3 = (const float*)d_in[11];
    float* out = (float*)d_out;

    float *A, *B, *H, *A3, *B3;
    cudaGetSymbolAddress((void**)&A, g_A);
    cudaGetSymbolAddress((void**)&B, g_B);
    cudaGetSymbolAddress((void**)&H, g_H);
    cudaGetSymbolAddress((void**)&A3, g_A3);
    cudaGetSymbolAddress((void**)&B3, g_B3);

    const int SMEM = (128 * 256 + 64 * 128) * 4;  // 160 KB
    cudaFuncSetAttribute(gemm_dual128, cudaFuncAttributeMaxDynamicSharedMemorySize, SMEM);

    const int gemm_grid = (N_NODES + 63) / 64;
    const int warp_grid = (N_NODES * 32 + 255) / 256;  // warp per node

    // ---- CSR build + counts ----
    zero_misc_kernel<<<(N_NODES + 255) / 256, 256>>>();
    count_deg_kernel<<<(N_EDGES + 255) / 256, 256>>>(ei);
    gcnt_kernel<<<(N_NODES + 255) / 256, 256>>>(batch);
    scan_kernel<<<1, 1024>>>();
    fill_csr_kernel<<<(N_EDGES + 255) / 256, 256>>>(ei);

    // ---- layer 1 ----
    gemm_dual128<<<gemm_grid, 256, SMEM>>>(x, Wl1, Wr1, A, B);
    gather_fin128<<<warp_grid, 256>>>(A, B, bl1, H);

    // ---- layer 2 ----
    gemm_dual128<<<gemm_grid, 256, SMEM>>>(H, Wl2, Wr2, A, B);
    gather_fin128<<<warp_grid, 256>>>(A, B, bl2, H);

    // ---- layer 3 (aggregate post-GEMM: 10-dim instead of 128-dim) ----
    gemm_dual10<<<warp_grid, 256>>>(H, Wl3, Wr3, A3, B3);
    gather10_pool<<<warp_grid, 256>>>(A3, B3, bl3, batch);

    final_out_kernel<<<1, 256>>>(out);
}

// round 4
// speedup vs baseline: 8.2238x; 1.2676x over previous
#include <cuda_runtime.h>

#define N_NODES 50000
#define N_EDGES 800000
#define F_IN 128
#define HIDDEN 128
#define N_CLASSES 10
#define N_GRAPHS 256
#define SCAN_BLOCKS 196  // ceil(50000/256)

// -------- scratch (static device globals) --------
__device__ int g_degi[N_NODES];
__device__ int g_off[N_NODES + 1];
__device__ int g_cur[N_NODES];
__device__ int g_bsum[256];  // block sums for scan (196 used)
__device__ int g_csr_src[N_EDGES];
__device__ float g_gcnt[N_GRAPHS];
__device__ float g_pool[N_GRAPHS * N_CLASSES];
__device__ __align__(16) float g_A[N_NODES * HIDDEN];
__device__ __align__(16) float g_B[N_NODES * HIDDEN];
__device__ __align__(16) float g_H[N_NODES * HIDDEN];
__device__ float g_A3[N_NODES * N_CLASSES];
__device__ float g_B3[N_NODES * N_CLASSES];

// -------- zero + fused counts --------
__global__ void zero_misc_kernel() {
    int i = blockIdx.x * blockDim.x + threadIdx.x;
    if (i < N_NODES) g_degi[i] = 0;
    if (i < N_GRAPHS) g_gcnt[i] = 0.f;
    if (i < N_GRAPHS * N_CLASSES) g_pool[i] = 0.f;
}

__global__ void count_kernel(const int* __restrict__ ei, const int* __restrict__ batch) {
    int e = blockIdx.x * blockDim.x + threadIdx.x;
    if (e < N_EDGES) atomicAdd(&g_degi[ei[N_EDGES + e]], 1);
    if (e < N_NODES) atomicAdd(&g_gcnt[batch[e]], 1.0f);
}

// -------- 3-phase parallel exclusive scan over degrees --------
__global__ __launch_bounds__(256) void scan1_kernel() {
    __shared__ int ws[8];
    const int t = threadIdx.x;
    const int lane = t & 31;
    const int warp = t >> 5;
    const int i = blockIdx.x * 256 + t;
    int v = (i < N_NODES) ? g_degi[i] : 0;
    int x = v;
#pragma unroll
    for (int off = 1; off < 32; off <<= 1) {
        int y = __shfl_up_sync(0xFFFFFFFFu, x, off);
        if (lane >= off) x += y;
    }
    if (lane == 31) ws[warp] = x;
    __syncthreads();
    if (warp == 0 && lane < 8) {
        int s = ws[lane];
#pragma unroll
        for (int off = 1; off < 8; off <<= 1) {
            int y = __shfl_up_sync(0xFFu, s, off);
            if (lane >= off) s += y;
        }
        ws[lane] = s;
    }
    __syncthreads();
    int incl = x + (warp > 0 ? ws[warp - 1] : 0);
    if (i < N_NODES) g_off[i] = incl - v;  // block-local exclusive
    if (t == 255) g_bsum[blockIdx.x] = incl;
}

__global__ __launch_bounds__(256) void scan2_kernel() {
    __shared__ int ws[8];
    const int t = threadIdx.x;
    const int lane = t & 31;
    const int warp = t >> 5;
    int v = (t < SCAN_BLOCKS) ? g_bsum[t] : 0;
    int x = v;
#pragma unroll
    for (int off = 1; off < 32; off <<= 1) {
        int y = __shfl_up_sync(0xFFFFFFFFu, x, off);
        if (lane >= off) x += y;
    }
    if (lane == 31) ws[warp] = x;
    __syncthreads();
    if (warp == 0 && lane < 8) {
        int s = ws[lane];
#pragma unroll
        for (int off = 1; off < 8; off <<= 1) {
            int y = __shfl_up_sync(0xFFu, s, off);
            if (lane >= off) s += y;
        }
        ws[lane] = s;
    }
    __syncthreads();
    int incl = x + (warp > 0 ? ws[warp - 1] : 0);
    g_bsum[t] = incl - v;  // exclusive block offsets
}

__global__ void scan3_kernel() {
    int i = blockIdx.x * blockDim.x + threadIdx.x;
    if (i < N_NODES) {
        int o = g_off[i] + g_bsum[i >> 8];
        g_off[i] = o;
        g_cur[i] = o;
    }
    if (i == 0) g_off[N_NODES] = N_EDGES;
}

__global__ void fill_csr_kernel(const int* __restrict__ ei) {
    int e = blockIdx.x * blockDim.x + threadIdx.x;
    if (e >= N_EDGES) return;
    int src = ei[e];
    int dst = ei[N_EDGES + e];
    int slot = atomicAdd(&g_cur[dst], 1);
    g_csr_src[slot] = src;
}

// -------- dual GEMM: A = X@Wl, B = X@Wr (Din=128, Dout=128 each) --------
__global__ __launch_bounds__(256) void gemm_dual128(
    const float* __restrict__ X, const float* __restrict__ Wl,
    const float* __restrict__ Wr, float* __restrict__ A, float* __restrict__ B) {
    extern __shared__ float sm[];
    float* Ws = sm;               // [128][256]
    float* Xs = sm + 128 * 256;   // [64][128]
    float4* Ws4 = (float4*)Ws;
    const int tid = threadIdx.x;

    for (int i = tid; i < 128 * 128 / 4; i += 256) {
        int k = (i * 4) >> 7;
        int c = (i * 4) & 127;
        float4 wl = ((const float4*)Wl)[i];
        float4 wr = ((const float4*)Wr)[i];
        *((float4*)&Ws[k * 256 + c]) = wl;
        *((float4*)&Ws[k * 256 + 128 + c]) = wr;
    }
    const int row0 = blockIdx.x * 64;
    for (int i = tid; i < 64 * 32; i += 256) {
        int r = i >> 5;
        int c4 = i & 31;
        int gr = row0 + r;
        float4 v = (gr < N_NODES) ? ((const float4*)X)[gr * 32 + c4]
                                  : make_float4(0.f, 0.f, 0.f, 0.f);
        *((float4*)&Xs[r * 128 + c4 * 4]) = v;
    }
    __syncthreads();

    const int tx = tid & 31;
    const int ty = tid >> 5;
    float acc[8][8];
#pragma unroll
    for (int i = 0; i < 8; i++)
#pragma unroll
        for (int j = 0; j < 8; j++) acc[i][j] = 0.f;

#pragma unroll 2
    for (int k = 0; k < 128; k++) {
        float xv[8];
#pragma unroll
        for (int i = 0; i < 8; i++) xv[i] = Xs[(ty * 8 + i) * 128 + k];
        float4 w0 = Ws4[k * 64 + tx * 2];
        float4 w1 = Ws4[k * 64 + tx * 2 + 1];
#pragma unroll
        for (int i = 0; i < 8; i++) {
            acc[i][0] += xv[i] * w0.x;
            acc[i][1] += xv[i] * w0.y;
            acc[i][2] += xv[i] * w0.z;
            acc[i][3] += xv[i] * w0.w;
            acc[i][4] += xv[i] * w1.x;
            acc[i][5] += xv[i] * w1.y;
            acc[i][6] += xv[i] * w1.z;
            acc[i][7] += xv[i] * w1.w;
        }
    }

    const int col = tx * 8;
#pragma unroll
    for (int i = 0; i < 8; i++) {
        int gr = row0 + ty * 8 + i;
        if (gr >= N_NODES) break;
        float* base = (col < 128) ? (A + gr * 128 + col) : (B + gr * 128 + col - 128);
        ((float4*)base)[0] = make_float4(acc[i][0], acc[i][1], acc[i][2], acc[i][3]);
        ((float4*)base)[1] = make_float4(acc[i][4], acc[i][5], acc[i][6], acc[i][7]);
    }
}

// -------- CSR gather + finalize: H = mean A[src] + B + bias --------
__global__ __launch_bounds__(256) void gather_fin128(
    const float* __restrict__ A, const float* __restrict__ B,
    const float* __restrict__ bias, float* __restrict__ H) {
    int warp = (blockIdx.x * blockDim.x + threadIdx.x) >> 5;
    int lane = threadIdx.x & 31;
    if (warp >= N_NODES) return;
    const int beg = g_off[warp];
    const int end = g_off[warp + 1];
    const float4* A4 = (const float4*)A;
    float4 acc = make_float4(0.f, 0.f, 0.f, 0.f);
    int j = beg;
    for (; j + 1 < end; j += 2) {
        int s0 = g_csr_src[j];
        int s1 = g_csr_src[j + 1];
        float4 v0 = A4[s0 * 32 + lane];
        float4 v1 = A4[s1 * 32 + lane];
        acc.x += v0.x + v1.x;
        acc.y += v0.y + v1.y;
        acc.z += v0.z + v1.z;
        acc.w += v0.w + v1.w;
    }
    if (j < end) {
        float4 v = A4[g_csr_src[j] * 32 + lane];
        acc.x += v.x; acc.y += v.y; acc.z += v.z; acc.w += v.w;
    }
    int deg = end - beg;
    float inv = 1.0f / (float)(deg > 1 ? deg : 1);
    float4 b = ((const float4*)B)[warp * 32 + lane];
    float4 bi = ((const float4*)bias)[lane];
    float4 h;
    h.x = acc.x * inv + b.x + bi.x;
    h.y = acc.y * inv + b.y + bi.y;
    h.z = acc.z * inv + b.z + bi.z;
    h.w = acc.w * inv + b.w + bi.w;
    ((float4*)H)[warp * 32 + lane] = h;
}

// -------- layer-3 dual GEMM: thread per node, weights in smem --------
__global__ __launch_bounds__(256) void gemm_dual10(
    const float* __restrict__ X, const float* __restrict__ Wl,
    const float* __restrict__ Wr, float* __restrict__ A, float* __restrict__ B) {
    __shared__ float sW[128 * 20];  // [k][0:10]=Wl, [k][10:20]=Wr
    const int tid = threadIdx.x;
    for (int i = tid; i < 128 * 10; i += 256) {
        int k = i / 10;
        int c = i - k * 10;
        sW[k * 20 + c] = Wl[i];
        sW[k * 20 + 10 + c] = Wr[i];
    }
    __syncthreads();
    int n = blockIdx.x * 256 + tid;
    if (n >= N_NODES) return;
    float accA[10], accB[10];
#pragma unroll
    for (int c = 0; c < 10; c++) { accA[c] = 0.f; accB[c] = 0.f; }
    const float4* X4 = (const float4*)X;
#pragma unroll 4
    for (int k4 = 0; k4 < 32; k4++) {
        float4 h = X4[n * 32 + k4];
        float hv[4] = {h.x, h.y, h.z, h.w};
#pragma unroll
        for (int j = 0; j < 4; j++) {
            const float* w = &sW[(k4 * 4 + j) * 20];
#pragma unroll
            for (int c = 0; c < 10; c++) {
                accA[c] += hv[j] * w[c];
                accB[c] += hv[j] * w[10 + c];
            }
        }
    }
#pragma unroll
    for (int c = 0; c < 10; c++) {
        A[n * 10 + c] = accA[c];
        B[n * 10 + c] = accB[c];
    }
}

// -------- layer-3 gather + finalize + graph pool (16 threads/node) --------
__global__ __launch_bounds__(256) void gather10_pool(
    const float* __restrict__ A3, const float* __restrict__ B3,
    const float* __restrict__ bl3, const int* __restrict__ batch) {
    int gid = blockIdx.x * blockDim.x + threadIdx.x;
    int node = gid >> 4;
    int lane = gid & 15;
    if (node >= N_NODES || lane >= N_CLASSES) return;
    const int beg = g_off[node];
    const int end = g_off[node + 1];
    float acc = 0.f;
    for (int j = beg; j < end; j++)
        acc += A3[g_csr_src[j] * N_CLASSES + lane];
    int deg = end - beg;
    float inv = 1.0f / (float)(deg > 1 ? deg : 1);
    float h = acc * inv + B3[node * N_CLASSES + lane] + bl3[lane];
    atomicAdd(&g_pool[batch[node] * N_CLASSES + lane], h);
}

// -------- pooled mean + log_softmax --------
__global__ void final_out_kernel(float* __restrict__ out) {
    int g = threadIdx.x;
    if (g >= N_GRAPHS) return;
    float cnt = g_gcnt[g];
    float inv = 1.0f / (cnt > 1.0f ? cnt : 1.0f);
    float v[N_CLASSES];
    float mx = -1e30f;
#pragma unroll
    for (int c = 0; c < N_CLASSES; c++) {
        v[c] = g_pool[g * N_CLASSES + c] * inv;
        mx = v[c] > mx ? v[c] : mx;
    }
    float s = 0.f;
#pragma unroll
    for (int c = 0; c < N_CLASSES; c++) s += expf(v[c] - mx);
    float ls = logf(s);
#pragma unroll
    for (int c = 0; c < N_CLASSES; c++) out[g * N_CLASSES + c] = v[c] - mx - ls;
}

// -------- host launch --------
extern "C" void kernel_launch(void* const* d_in, const int* in_sizes, int n_in,
                              void* d_out, int out_size) {
    const float* x = (const float*)d_in[0];
    const int* ei = (const int*)d_in[1];
    const int* batch = (const int*)d_in[2];
    const float* Wl1 = (const float*)d_in[3];
    const float* bl1 = (const float*)d_in[4];
    const float* Wr1 = (const float*)d_in[5];
    const float* Wl2 = (const float*)d_in[6];
    const float* bl2 = (const float*)d_in[7];
    const float* Wr2 = (const float*)d_in[8];
    const float* Wl3 = (const float*)d_in[9];
    const float* bl3 = (const float*)d_in[10];
    const float* Wr3 = (const float*)d_in[11];
    float* out = (float*)d_out;

    float *A, *B, *H, *A3, *B3;
    cudaGetSymbolAddress((void**)&A, g_A);
    cudaGetSymbolAddress((void**)&B, g_B);
    cudaGetSymbolAddress((void**)&H, g_H);
    cudaGetSymbolAddress((void**)&A3, g_A3);
    cudaGetSymbolAddress((void**)&B3, g_B3);

    const int SMEM = (128 * 256 + 64 * 128) * 4;  // 160 KB
    cudaFuncSetAttribute(gemm_dual128, cudaFuncAttributeMaxDynamicSharedMemorySize, SMEM);

    const int gemm_grid = (N_NODES + 63) / 64;
    const int warp_grid = (N_NODES * 32 + 255) / 256;

    // ---- CSR build + counts ----
    zero_misc_kernel<<<(N_NODES + 255) / 256, 256>>>();
    count_kernel<<<(N_EDGES + 255) / 256, 256>>>(ei, batch);
    scan1_kernel<<<SCAN_BLOCKS, 256>>>();
    scan2_kernel<<<1, 256>>>();
    scan3_kernel<<<SCAN_BLOCKS, 256>>>();
    fill_csr_kernel<<<(N_EDGES + 255) / 256, 256>>>(ei);

    // ---- layer 1 ----
    gemm_dual128<<<gemm_grid, 256, SMEM>>>(x, Wl1, Wr1, A, B);
    gather_fin128<<<warp_grid, 256>>>(A, B, bl1, H);

    // ---- layer 2 ----
    gemm_dual128<<<gemm_grid, 256, SMEM>>>(H, Wl2, Wr2, A, B);
    gather_fin128<<<warp_grid, 256>>>(A, B, bl2, H);

    // ---- layer 3 (aggregate post-GEMM: 10-dim) ----
    gemm_dual10<<<(N_NODES + 255) / 256, 256>>>(H, Wl3, Wr3, A3, B3);
    gather10_pool<<<(N_NODES * 16 + 255) / 256, 256>>>(A3, B3, bl3, batch);

    final_out_kernel<<<1, 256>>>(out);
}

// round 6
// speedup vs baseline: 9.2624x; 1.1263x over previous
#include <cuda_runtime.h>
#include <cstdint>

#define N_NODES 50000
#define N_EDGES 800000
#define F_IN 128
#define HIDDEN 128
#define N_CLASSES 10
#define N_GRAPHS 256
#define SCAN_BLOCKS 196  // ceil(50000/256)

#define XS_STRIDE 132  // bank map 4*g+tg -> conflict-free A frags
#define WS_STRIDE 136  // bank map 8*tg+g -> conflict-free B frags

// -------- scratch (static device globals) --------
__device__ int g_degi[N_NODES];
__device__ int g_off[N_NODES + 1];
__device__ int g_cur[N_NODES];
__device__ int g_bsum[256];
__device__ int g_csr_src[N_EDGES];
__device__ float g_gcnt[N_GRAPHS];
__device__ float g_pool[N_GRAPHS * N_CLASSES];
__device__ __align__(16) float g_A[N_NODES * HIDDEN];
__device__ __align__(16) float g_B[N_NODES * HIDDEN];
__device__ __align__(16) float g_H[N_NODES * HIDDEN];
__device__ float g_A3[N_NODES * N_CLASSES];
__device__ float g_B3[N_NODES * N_CLASSES];

// -------- zero + fused counts --------
__global__ void zero_misc_kernel() {
    int i = blockIdx.x * blockDim.x + threadIdx.x;
    if (i < N_NODES) g_degi[i] = 0;
    if (i < N_GRAPHS) g_gcnt[i] = 0.f;
    if (i < N_GRAPHS * N_CLASSES) g_pool[i] = 0.f;
}

__global__ void count_kernel(const int* __restrict__ ei, const int* __restrict__ batch) {
    int e = blockIdx.x * blockDim.x + threadIdx.x;
    if (e < N_EDGES) atomicAdd(&g_degi[ei[N_EDGES + e]], 1);
    if (e < N_NODES) atomicAdd(&g_gcnt[batch[e]], 1.0f);
}

// -------- 3-phase parallel exclusive scan over degrees --------
__global__ __launch_bounds__(256) void scan1_kernel() {
    __shared__ int ws[8];
    const int t = threadIdx.x;
    const int lane = t & 31;
    const int warp = t >> 5;
    const int i = blockIdx.x * 256 + t;
    int v = (i < N_NODES) ? g_degi[i] : 0;
    int x = v;
#pragma unroll
    for (int off = 1; off < 32; off <<= 1) {
        int y = __shfl_up_sync(0xFFFFFFFFu, x, off);
        if (lane >= off) x += y;
    }
    if (lane == 31) ws[warp] = x;
    __syncthreads();
    if (warp == 0 && lane < 8) {
        int s = ws[lane];
#pragma unroll
        for (int off = 1; off < 8; off <<= 1) {
            int y = __shfl_up_sync(0xFFu, s, off);
            if (lane >= off) s += y;
        }
        ws[lane] = s;
    }
    __syncthreads();
    int incl = x + (warp > 0 ? ws[warp - 1] : 0);
    if (i < N_NODES) g_off[i] = incl - v;
    if (t == 255) g_bsum[blockIdx.x] = incl;
}

__global__ __launch_bounds__(256) void scan2_kernel() {
    __shared__ int ws[8];
    const int t = threadIdx.x;
    const int lane = t & 31;
    const int warp = t >> 5;
    int v = (t < SCAN_BLOCKS) ? g_bsum[t] : 0;
    int x = v;
#pragma unroll
    for (int off = 1; off < 32; off <<= 1) {
        int y = __shfl_up_sync(0xFFFFFFFFu, x, off);
        if (lane >= off) x += y;
    }
    if (lane == 31) ws[warp] = x;
    __syncthreads();
    if (warp == 0 && lane < 8) {
        int s = ws[lane];
#pragma unroll
        for (int off = 1; off < 8; off <<= 1) {
            int y = __shfl_up_sync(0xFFu, s, off);
            if (lane >= off) s += y;
        }
        ws[lane] = s;
    }
    __syncthreads();
    int incl = x + (warp > 0 ? ws[warp - 1] : 0);
    g_bsum[t] = incl - v;
}

__global__ void scan3_kernel() {
    int i = blockIdx.x * blockDim.x + threadIdx.x;
    if (i < N_NODES) {
        int o = g_off[i] + g_bsum[i >> 8];
        g_off[i] = o;
        g_cur[i] = o;
    }
    if (i == 0) g_off[N_NODES] = N_EDGES;
}

__global__ void fill_csr_kernel(const int* __restrict__ ei) {
    int e = blockIdx.x * blockDim.x + threadIdx.x;
    if (e >= N_EDGES) return;
    int src = ei[e];
    int dst = ei[N_EDGES + e];
    int slot = atomicAdd(&g_cur[dst], 1);
    g_csr_src[slot] = src;
}

// ======== mma.sync tf32 dual GEMM (3xTF32 compensated) ========
__device__ __forceinline__ uint32_t tf32_hi(float x) {
    uint32_t u;
    asm("cvt.rna.tf32.f32 %0, %1;" : "=r"(u) : "f"(x));
    return u;
}
__device__ __forceinline__ void mma_tf32_frag(float* d, const uint32_t* a,
                                              uint32_t b0, uint32_t b1) {
    asm volatile(
        "mma.sync.aligned.m16n8k8.row.col.f32.tf32.tf32.f32 "
        "{%0,%1,%2,%3}, {%4,%5,%6,%7}, {%8,%9}, {%0,%1,%2,%3};"
        : "+f"(d[0]), "+f"(d[1]), "+f"(d[2]), "+f"(d[3])
        : "r"(a[0]), "r"(a[1]), "r"(a[2]), "r"(a[3]), "r"(b0), "r"(b1));
}

// grid (391, 2): y=0 -> Wl -> A; y=1 -> Wr -> B. 256 thr, 1 CTA/SM (207KB smem).
__global__ __launch_bounds__(256) void gemm_dual128_mma(
    const float* __restrict__ X, const float* __restrict__ Wl,
    const float* __restrict__ Wr, float* __restrict__ A, float* __restrict__ B) {
    extern __shared__ float sm[];
    float* Xs = sm;                               // [128][132] fp32
    float* Whi = sm + 128 * XS_STRIDE;            // [128][136] tf32-hi
    float* Wlo = Whi + 128 * WS_STRIDE;           // [128][136] tf32-lo
    const int tid = threadIdx.x;
    const float* W = blockIdx.y ? Wr : Wl;
    float* OUT = blockIdx.y ? B : A;
    const int row0 = blockIdx.x * 128;

    // stage X (fp32, padded)
    const float4* X4 = (const float4*)X;
    for (int i = tid; i < 128 * 32; i += 256) {
        int r = i >> 5, c4 = i & 31;
        int gr = row0 + r;
        float4 v = (gr < N_NODES) ? X4[gr * 32 + c4] : make_float4(0.f, 0.f, 0.f, 0.f);
        *(float4*)&Xs[r * XS_STRIDE + c4 * 4] = v;
    }
    // stage W split hi/lo
    const float4* W4 = (const float4*)W;
    for (int i = tid; i < 128 * 32; i += 256) {
        int k = i >> 5, c4 = i & 31, n0 = c4 * 4;
        float4 w = W4[i];
        float wv[4] = {w.x, w.y, w.z, w.w};
#pragma unroll
        for (int j = 0; j < 4; j++) {
            uint32_t h = tf32_hi(wv[j]);
            Whi[k * WS_STRIDE + n0 + j] = __uint_as_float(h);
            Wlo[k * WS_STRIDE + n0 + j] =
                __uint_as_float(tf32_hi(wv[j] - __uint_as_float(h)));
        }
    }
    __syncthreads();

    const int warp = tid >> 5, lane = tid & 31;
    const int mw = warp >> 1;       // 0..3 : rows mw*32..+32
    const int nw = warp & 1;        // 0..1 : cols nw*64..+64
    const int g = lane >> 2, tg = lane & 3;

    float acc[2][8][4];
#pragma unroll
    for (int mt = 0; mt < 2; mt++)
#pragma unroll
        for (int nt = 0; nt < 8; nt++)
#pragma unroll
            for (int q = 0; q < 4; q++) acc[mt][nt][q] = 0.f;

    for (int ks = 0; ks < 16; ks++) {
        const int k0 = ks * 8;
        uint32_t ahi[2][4], alo[2][4];
#pragma unroll
        for (int mt = 0; mt < 2; mt++) {
            int rb = mw * 32 + mt * 16;
            float x0 = Xs[(rb + g) * XS_STRIDE + k0 + tg];
            float x1 = Xs[(rb + g + 8) * XS_STRIDE + k0 + tg];
            float x2 = Xs[(rb + g) * XS_STRIDE + k0 + tg + 4];
            float x3 = Xs[(rb + g + 8) * XS_STRIDE + k0 + tg + 4];
            ahi[mt][0] = tf32_hi(x0);
            ahi[mt][1] = tf32_hi(x1);
            ahi[mt][2] = tf32_hi(x2);
            ahi[mt][3] = tf32_hi(x3);
            alo[mt][0] = tf32_hi(x0 - __uint_as_float(ahi[mt][0]));
            alo[mt][1] = tf32_hi(x1 - __uint_as_float(ahi[mt][1]));
            alo[mt][2] = tf32_hi(x2 - __uint_as_float(ahi[mt][2]));
            alo[mt][3] = tf32_hi(x3 - __uint_as_float(ahi[mt][3]));
        }
#pragma unroll
        for (int nt = 0; nt < 8; nt++) {
            int col = nw * 64 + nt * 8 + g;
            uint32_t bh0 = __float_as_uint(Whi[(k0 + tg) * WS_STRIDE + col]);
            uint32_t bh1 = __float_as_uint(Whi[(k0 + tg + 4) * WS_STRIDE + col]);
            uint32_t bl0 = __float_as_uint(Wlo[(k0 + tg) * WS_STRIDE + col]);
            uint32_t bl1 = __float_as_uint(Wlo[(k0 + tg + 4) * WS_STRIDE + col]);
#pragma unroll
            for (int mt = 0; mt < 2; mt++) {
                mma_tf32_frag(acc[mt][nt], ahi[mt], bh0, bh1);
                mma_tf32_frag(acc[mt][nt], alo[mt], bh0, bh1);
                mma_tf32_frag(acc[mt][nt], ahi[mt], bl0, bl1);
            }
        }
    }

    // epilogue: C[m16n8]: c0 row=g col=2tg; c1 col+1; c2 row=g+8; c3 col+1
#pragma unroll
    for (int mt = 0; mt < 2; mt++) {
        int gr0 = row0 + mw * 32 + mt * 16 + g;
        int gr1 = gr0 + 8;
#pragma unroll
        for (int nt = 0; nt < 8; nt++) {
            int gc = nw * 64 + nt * 8 + tg * 2;
            if (gr0 < N_NODES)
                *(float2*)&OUT[gr0 * 128 + gc] = make_float2(acc[mt][nt][0], acc[mt][nt][1]);
            if (gr1 < N_NODES)
                *(float2*)&OUT[gr1 * 128 + gc] = make_float2(acc[mt][nt][2], acc[mt][nt][3]);
        }
    }
}

// -------- CSR gather + finalize: H = mean A[src] + B + bias --------
__global__ __launch_bounds__(256) void gather_fin128(
    const float* __restrict__ A, const float* __restrict__ B,
    const float* __restrict__ bias, float* __restrict__ H) {
    int warp = (blockIdx.x * blockDim.x + threadIdx.x) >> 5;
    int lane = threadIdx.x & 31;
    if (warp >= N_NODES) return;
    const int beg = g_off[warp];
    const int end = g_off[warp + 1];
    const float4* A4 = (const float4*)A;
    float4 acc = make_float4(0.f, 0.f, 0.f, 0.f);
    int j = beg;
    for (; j + 1 < end; j += 2) {
        int s0 = g_csr_src[j];
        int s1 = g_csr_src[j + 1];
        float4 v0 = A4[s0 * 32 + lane];
        float4 v1 = A4[s1 * 32 + lane];
        acc.x += v0.x + v1.x;
        acc.y += v0.y + v1.y;
        acc.z += v0.z + v1.z;
        acc.w += v0.w + v1.w;
    }
    if (j < end) {
        float4 v = A4[g_csr_src[j] * 32 + lane];
        acc.x += v.x; acc.y += v.y; acc.z += v.z; acc.w += v.w;
    }
    int deg = end - beg;
    float inv = 1.0f / (float)(deg > 1 ? deg : 1);
    float4 b = ((const float4*)B)[warp * 32 + lane];
    float4 bi = ((const float4*)bias)[lane];
    float4 h;
    h.x = acc.x * inv + b.x + bi.x;
    h.y = acc.y * inv + b.y + bi.y;
    h.z = acc.z * inv + b.z + bi.z;
    h.w = acc.w * inv + b.w + bi.w;
    ((float4*)H)[warp * 32 + lane] = h;
}

// -------- layer-3 dual GEMM: thread per node, weights in smem --------
__global__ __launch_bounds__(256) void gemm_dual10(
    const float* __restrict__ X, const float* __restrict__ Wl,
    const float* __restrict__ Wr, float* __restrict__ A, float* __restrict__ B) {
    __shared__ float sW[128 * 20];
    const int tid = threadIdx.x;
    for (int i = tid; i < 128 * 10; i += 256) {
        int k = i / 10;
        int c = i - k * 10;
        sW[k * 20 + c] = Wl[i];
        sW[k * 20 + 10 + c] = Wr[i];
    }
    __syncthreads();
    int n = blockIdx.x * 256 + tid;
    if (n >= N_NODES) return;
    float accA[10], accB[10];
#pragma unroll
    for (int c = 0; c < 10; c++) { accA[c] = 0.f; accB[c] = 0.f; }
    const float4* X4 = (const float4*)X;
#pragma unroll 4
    for (int k4 = 0; k4 < 32; k4++) {
        float4 h = X4[n * 32 + k4];
        float hv[4] = {h.x, h.y, h.z, h.w};
#pragma unroll
        for (int j = 0; j < 4; j++) {
            const float* w = &sW[(k4 * 4 + j) * 20];
#pragma unroll
            for (int c = 0; c < 10; c++) {
                accA[c] += hv[j] * w[c];
                accB[c] += hv[j] * w[10 + c];
            }
        }
    }
#pragma unroll
    for (int c = 0; c < 10; c++) {
        A[n * 10 + c] = accA[c];
        B[n * 10 + c] = accB[c];
    }
}

// -------- layer-3 gather + finalize + graph pool (16 threads/node) --------
__global__ __launch_bounds__(256) void gather10_pool(
    const float* __restrict__ A3, const float* __restrict__ B3,
    const float* __restrict__ bl3, const int* __restrict__ batch) {
    int gid = blockIdx.x * blockDim.x + threadIdx.x;
    int node = gid >> 4;
    int lane = gid & 15;
    if (node >= N_NODES || lane >= N_CLASSES) return;
    const int beg = g_off[node];
    const int end = g_off[node + 1];
    float acc = 0.f;
    for (int j = beg; j < end; j++)
        acc += A3[g_csr_src[j] * N_CLASSES + lane];
    int deg = end - beg;
    float inv = 1.0f / (float)(deg > 1 ? deg : 1);
    float h = acc * inv + B3[node * N_CLASSES + lane] + bl3[lane];
    atomicAdd(&g_pool[batch[node] * N_CLASSES + lane], h);
}

// -------- pooled mean + log_softmax --------
__global__ void final_out_kernel(float* __restrict__ out) {
    int g = threadIdx.x;
    if (g >= N_GRAPHS) return;
    float cnt = g_gcnt[g];
    float inv = 1.0f / (cnt > 1.0f ? cnt : 1.0f);
    float v[N_CLASSES];
    float mx = -1e30f;
#pragma unroll
    for (int c = 0; c < N_CLASSES; c++) {
        v[c] = g_pool[g * N_CLASSES + c] * inv;
        mx = v[c] > mx ? v[c] : mx;
    }
    float s = 0.f;
#pragma unroll
    for (int c = 0; c < N_CLASSES; c++) s += expf(v[c] - mx);
    float ls = logf(s);
#pragma unroll
    for (int c = 0; c < N_CLASSES; c++) out[g * N_CLASSES + c] = v[c] - mx - ls;
}

// -------- host launch --------
extern "C" void kernel_launch(void* const* d_in, const int* in_sizes, int n_in,
                              void* d_out, int out_size) {
    const float* x = (const float*)d_in[0];
    const int* ei = (const int*)d_in[1];
    const int* batch = (const int*)d_in[2];
    const float* Wl1 = (const float*)d_in[3];
    const float* bl1 = (const float*)d_in[4];
    const float* Wr1 = (const float*)d_in[5];
    const float* Wl2 = (const float*)d_in[6];
    const float* bl2 = (const float*)d_in[7];
    const float* Wr2 = (const float*)d_in[8];
    const float* Wl3 = (const float*)d_in[9];
    const float* bl3 = (const float*)d_in[10];
    const float* Wr3 = (const float*)d_in[11];
    float* out = (float*)d_out;

    float *A, *B, *H, *A3, *B3;
    cudaGetSymbolAddress((void**)&A, g_A);
    cudaGetSymbolAddress((void**)&B, g_B);
    cudaGetSymbolAddress((void**)&H, g_H);
    cudaGetSymbolAddress((void**)&A3, g_A3);
    cudaGetSymbolAddress((void**)&B3, g_B3);

    const int SMEM_MMA = (128 * XS_STRIDE + 2 * 128 * WS_STRIDE) * 4;  // 206848
    cudaFuncSetAttribute(gemm_dual128_mma, cudaFuncAttributeMaxDynamicSharedMemorySize,
                         SMEM_MMA);

    const dim3 mma_grid((N_NODES + 127) / 128, 2);
    const int warp_grid = (N_NODES * 32 + 255) / 256;

    // ---- CSR build + counts ----
    zero_misc_kernel<<<(N_NODES + 255) / 256, 256>>>();
    count_kernel<<<(N_EDGES + 255) / 256, 256>>>(ei, batch);
    scan1_kernel<<<SCAN_BLOCKS, 256>>>();
    scan2_kernel<<<1, 256>>>();
    scan3_kernel<<<SCAN_BLOCKS, 256>>>();
    fill_csr_kernel<<<(N_EDGES + 255) / 256, 256>>>(ei);

    // ---- layer 1 ----
    gemm_dual128_mma<<<mma_grid, 256, SMEM_MMA>>>(x, Wl1, Wr1, A, B);
    gather_fin128<<<warp_grid, 256>>>(A, B, bl1, H);

    // ---- layer 2 ----
    gemm_dual128_mma<<<mma_grid, 256, SMEM_MMA>>>(H, Wl2, Wr2, A, B);
    gather_fin128<<<warp_grid, 256>>>(A, B, bl2, H);

    // ---- layer 3 (aggregate post-GEMM: 10-dim) ----
    gemm_dual10<<<(N_NODES + 255) / 256, 256>>>(H, Wl3, Wr3, A3, B3);
    gather10_pool<<<(N_NODES * 16 + 255) / 256, 256>>>(A3, B3, bl3, batch);

    final_out_kernel<<<1, 256>>>(out);
}

// round 7
// speedup vs baseline: 12.3641x; 1.3349x over previous
#include <cuda_runtime.h>
#include <cuda_bf16.h>
#include <cstdint>

#define N_NODES 50000
#define N_EDGES 800000
#define F_IN 128
#define HIDDEN 128
#define N_CLASSES 10
#define N_GRAPHS 256
#define SCAN_BLOCKS 196  // ceil(50000/256)

#define TW 68  // words (bf16x2) per row in smem tiles: 64 data + 4 pad

// -------- scratch (static device globals) --------
__device__ int g_degi[N_NODES];
__device__ int g_off[N_NODES + 1];
__device__ int g_cur[N_NODES];
__device__ int g_bsum[256];
__device__ int g_csr_src[N_EDGES];
__device__ float g_gcnt[N_GRAPHS];
__device__ float g_pool[N_GRAPHS * N_CLASSES];
__device__ __align__(16) float g_A[N_NODES * HIDDEN];
__device__ __align__(16) float g_B[N_NODES * HIDDEN];
__device__ __align__(16) float g_H[N_NODES * HIDDEN];
__device__ float g_A3[N_NODES * N_CLASSES];
__device__ float g_B3[N_NODES * N_CLASSES];

// -------- zero + fused counts --------
__global__ void zero_misc_kernel() {
    int i = blockIdx.x * blockDim.x + threadIdx.x;
    if (i < N_NODES) g_degi[i] = 0;
    if (i < N_GRAPHS) g_gcnt[i] = 0.f;
    if (i < N_GRAPHS * N_CLASSES) g_pool[i] = 0.f;
}

__global__ void count_kernel(const int* __restrict__ ei, const int* __restrict__ batch) {
    int e = blockIdx.x * blockDim.x + threadIdx.x;
    if (e < N_EDGES) atomicAdd(&g_degi[ei[N_EDGES + e]], 1);
    if (e < N_NODES) atomicAdd(&g_gcnt[batch[e]], 1.0f);
}

// -------- 3-phase parallel exclusive scan over degrees --------
__global__ __launch_bounds__(256) void scan1_kernel() {
    __shared__ int ws[8];
    const int t = threadIdx.x;
    const int lane = t & 31;
    const int warp = t >> 5;
    const int i = blockIdx.x * 256 + t;
    int v = (i < N_NODES) ? g_degi[i] : 0;
    int x = v;
#pragma unroll
    for (int off = 1; off < 32; off <<= 1) {
        int y = __shfl_up_sync(0xFFFFFFFFu, x, off);
        if (lane >= off) x += y;
    }
    if (lane == 31) ws[warp] = x;
    __syncthreads();
    if (warp == 0 && lane < 8) {
        int s = ws[lane];
#pragma unroll
        for (int off = 1; off < 8; off <<= 1) {
            int y = __shfl_up_sync(0xFFu, s, off);
            if (lane >= off) s += y;
        }
        ws[lane] = s;
    }
    __syncthreads();
    int incl = x + (warp > 0 ? ws[warp - 1] : 0);
    if (i < N_NODES) g_off[i] = incl - v;
    if (t == 255) g_bsum[blockIdx.x] = incl;
}

__global__ __launch_bounds__(256) void scan2_kernel() {
    __shared__ int ws[8];
    const int t = threadIdx.x;
    const int lane = t & 31;
    const int warp = t >> 5;
    int v = (t < SCAN_BLOCKS) ? g_bsum[t] : 0;
    int x = v;
#pragma unroll
    for (int off = 1; off < 32; off <<= 1) {
        int y = __shfl_up_sync(0xFFFFFFFFu, x, off);
        if (lane >= off) x += y;
    }
    if (lane == 31) ws[warp] = x;
    __syncthreads();
    if (warp == 0 && lane < 8) {
        int s = ws[lane];
#pragma unroll
        for (int off = 1; off < 8; off <<= 1) {
            int y = __shfl_up_sync(0xFFu, s, off);
            if (lane >= off) s += y;
        }
        ws[lane] = s;
    }
    __syncthreads();
    int incl = x + (warp > 0 ? ws[warp - 1] : 0);
    g_bsum[t] = incl - v;
}

__global__ void scan3_kernel() {
    int i = blockIdx.x * blockDim.x + threadIdx.x;
    if (i < N_NODES) {
        int o = g_off[i] + g_bsum[i >> 8];
        g_off[i] = o;
        g_cur[i] = o;
    }
    if (i == 0) g_off[N_NODES] = N_EDGES;
}

__global__ void fill_csr_kernel(const int* __restrict__ ei) {
    int e = blockIdx.x * blockDim.x + threadIdx.x;
    if (e >= N_EDGES) return;
    int src = ei[e];
    int dst = ei[N_EDGES + e];
    int slot = atomicAdd(&g_cur[dst], 1);
    g_csr_src[slot] = src;
}

// ======== bf16 mma.sync dual GEMM (3-term compensated) ========
__device__ __forceinline__ uint32_t pack_hi(float a, float b) {
    __nv_bfloat162 h = __floats2bfloat162_rn(a, b);
    return *(uint32_t*)&h;
}
__device__ __forceinline__ uint32_t pack_lo(float a, float b, uint32_t hi) {
    __nv_bfloat162 h = *(__nv_bfloat162*)&hi;
    __nv_bfloat162 l =
        __floats2bfloat162_rn(a - __bfloat162float(h.x), b - __bfloat162float(h.y));
    return *(uint32_t*)&l;
}
__device__ __forceinline__ void mma_bf16(float* d, const uint32_t* a, uint32_t b0,
                                         uint32_t b1) {
    asm volatile(
        "mma.sync.aligned.m16n8k16.row.col.f32.bf16.bf16.f32 "
        "{%0,%1,%2,%3}, {%4,%5,%6,%7}, {%8,%9}, {%0,%1,%2,%3};"
        : "+f"(d[0]), "+f"(d[1]), "+f"(d[2]), "+f"(d[3])
        : "r"(a[0]), "r"(a[1]), "r"(a[2]), "r"(a[3]), "r"(b0), "r"(b1));
}

// One CTA: 128 rows x (Wl 128 cols + Wr 128 cols), K=128. 256 threads, 204KB smem.
// Smem word layout (uint32 = bf16x2 pair along k): Xhi, Xlo, WhiL, WloL, WhiR, WloR,
// each [128][TW] words; W tiles are [n][k] (transposed).
__global__ __launch_bounds__(256) void gemm_dual128_bf16(
    const float* __restrict__ X, const float* __restrict__ Wl,
    const float* __restrict__ Wr, float* __restrict__ A, float* __restrict__ B) {
    extern __shared__ uint32_t smw[];
    uint32_t* Xhi = smw;
    uint32_t* Xlo = smw + 128 * TW;
    uint32_t* Wtiles[4] = {smw + 2 * 128 * TW, smw + 3 * 128 * TW,
                           smw + 4 * 128 * TW, smw + 5 * 128 * TW};  // hiL, loL, hiR, loR
    const int tid = threadIdx.x;
    const int row0 = blockIdx.x * 128;

    // ---- stage X -> Xhi/Xlo (packed bf16x2 along k) ----
    const float4* X4 = (const float4*)X;
    for (int i = tid; i < 128 * 32; i += 256) {
        int r = i >> 5, c4 = i & 31;
        int gr = row0 + r;
        float4 v = (gr < N_NODES) ? X4[gr * 32 + c4] : make_float4(0.f, 0.f, 0.f, 0.f);
        uint32_t h0 = pack_hi(v.x, v.y), h1 = pack_hi(v.z, v.w);
        Xhi[r * TW + 2 * c4] = h0;
        Xhi[r * TW + 2 * c4 + 1] = h1;
        Xlo[r * TW + 2 * c4] = pack_lo(v.x, v.y, h0);
        Xlo[r * TW + 2 * c4 + 1] = pack_lo(v.z, v.w, h1);
    }
    // ---- stage W -> [n][k] transposed hi/lo ----
    for (int i = tid; i < 128 * 64; i += 256) {
        int n = i & 127, j = i >> 7;  // j = k-pair index
        float l0 = Wl[(2 * j) * 128 + n], l1 = Wl[(2 * j + 1) * 128 + n];
        float r0 = Wr[(2 * j) * 128 + n], r1 = Wr[(2 * j + 1) * 128 + n];
        uint32_t hl = pack_hi(l0, l1), hr = pack_hi(r0, r1);
        Wtiles[0][n * TW + j] = hl;
        Wtiles[1][n * TW + j] = pack_lo(l0, l1, hl);
        Wtiles[2][n * TW + j] = hr;
        Wtiles[3][n * TW + j] = pack_lo(r0, r1, hr);
    }
    __syncthreads();

    const int warp = tid >> 5, lane = tid & 31;
    const int mw = warp >> 1;  // 0..3: rows mw*32
    const int nw = warp & 1;   // 0..1: cols nw*64 (within 128-col phase)
    const int g = lane >> 2, tg = lane & 3;

    for (int phase = 0; phase < 2; phase++) {
        const uint32_t* Wh = Wtiles[phase * 2];
        const uint32_t* Wo = Wtiles[phase * 2 + 1];
        float* OUT = phase ? B : A;

        float acc[2][8][4];
#pragma unroll
        for (int mt = 0; mt < 2; mt++)
#pragma unroll
            for (int nt = 0; nt < 8; nt++)
#pragma unroll
                for (int q = 0; q < 4; q++) acc[mt][nt][q] = 0.f;

#pragma unroll
        for (int ks = 0; ks < 8; ks++) {  // k16 steps
            const int j0 = ks * 8;
            uint32_t ahi[2][4], alo[2][4];
#pragma unroll
            for (int mt = 0; mt < 2; mt++) {
                int rb = mw * 32 + mt * 16;
                ahi[mt][0] = Xhi[(rb + g) * TW + j0 + tg];
                ahi[mt][1] = Xhi[(rb + 8 + g) * TW + j0 + tg];
                ahi[mt][2] = Xhi[(rb + g) * TW + j0 + 4 + tg];
                ahi[mt][3] = Xhi[(rb + 8 + g) * TW + j0 + 4 + tg];
                alo[mt][0] = Xlo[(rb + g) * TW + j0 + tg];
                alo[mt][1] = Xlo[(rb + 8 + g) * TW + j0 + tg];
                alo[mt][2] = Xlo[(rb + g) * TW + j0 + 4 + tg];
                alo[mt][3] = Xlo[(rb + 8 + g) * TW + j0 + 4 + tg];
            }
#pragma unroll
            for (int nt = 0; nt < 8; nt++) {
                int col = nw * 64 + nt * 8 + g;
                uint32_t bh0 = Wh[col * TW + j0 + tg];
                uint32_t bh1 = Wh[col * TW + j0 + 4 + tg];
                uint32_t bl0 = Wo[col * TW + j0 + tg];
                uint32_t bl1 = Wo[col * TW + j0 + 4 + tg];
#pragma unroll
                for (int mt = 0; mt < 2; mt++) {
                    mma_bf16(acc[mt][nt], ahi[mt], bh0, bh1);
                    mma_bf16(acc[mt][nt], alo[mt], bh0, bh1);
                    mma_bf16(acc[mt][nt], ahi[mt], bl0, bl1);
                }
            }
        }

        // epilogue: c0,c1 -> row g, cols 2tg,2tg+1; c2,c3 -> row g+8
#pragma unroll
        for (int mt = 0; mt < 2; mt++) {
            int gr0 = row0 + mw * 32 + mt * 16 + g;
            int gr1 = gr0 + 8;
#pragma unroll
            for (int nt = 0; nt < 8; nt++) {
                int gc = nw * 64 + nt * 8 + tg * 2;
                if (gr0 < N_NODES)
                    *(float2*)&OUT[gr0 * 128 + gc] =
                        make_float2(acc[mt][nt][0], acc[mt][nt][1]);
                if (gr1 < N_NODES)
                    *(float2*)&OUT[gr1 * 128 + gc] =
                        make_float2(acc[mt][nt][2], acc[mt][nt][3]);
            }
        }
    }
}

// -------- CSR gather + finalize: H = mean A[src] + B + bias --------
__global__ __launch_bounds__(256) void gather_fin128(
    const float* __restrict__ A, const float* __restrict__ B,
    const float* __restrict__ bias, float* __restrict__ H) {
    int warp = (blockIdx.x * blockDim.x + threadIdx.x) >> 5;
    int lane = threadIdx.x & 31;
    if (warp >= N_NODES) return;
    const int beg = g_off[warp];
    const int end = g_off[warp + 1];
    const float4* A4 = (const float4*)A;
    float4 acc = make_float4(0.f, 0.f, 0.f, 0.f);
    int j = beg;
    for (; j + 1 < end; j += 2) {
        int s0 = g_csr_src[j];
        int s1 = g_csr_src[j + 1];
        float4 v0 = A4[s0 * 32 + lane];
        float4 v1 = A4[s1 * 32 + lane];
        acc.x += v0.x + v1.x;
        acc.y += v0.y + v1.y;
        acc.z += v0.z + v1.z;
        acc.w += v0.w + v1.w;
    }
    if (j < end) {
        float4 v = A4[g_csr_src[j] * 32 + lane];
        acc.x += v.x; acc.y += v.y; acc.z += v.z; acc.w += v.w;
    }
    int deg = end - beg;
    float inv = 1.0f / (float)(deg > 1 ? deg : 1);
    float4 b = ((const float4*)B)[warp * 32 + lane];
    float4 bi = ((const float4*)bias)[lane];
    float4 h;
    h.x = acc.x * inv + b.x + bi.x;
    h.y = acc.y * inv + b.y + bi.y;
    h.z = acc.z * inv + b.z + bi.z;
    h.w = acc.w * inv + b.w + bi.w;
    ((float4*)H)[warp * 32 + lane] = h;
}

// -------- layer-3 dual GEMM: thread per node, weights in smem --------
__global__ __launch_bounds__(256) void gemm_dual10(
    const float* __restrict__ X, const float* __restrict__ Wl,
    const float* __restrict__ Wr, float* __restrict__ A, float* __restrict__ B) {
    __shared__ float sW[128 * 20];
    const int tid = threadIdx.x;
    for (int i = tid; i < 128 * 10; i += 256) {
        int k = i / 10;
        int c = i - k * 10;
        sW[k * 20 + c] = Wl[i];
        sW[k * 20 + 10 + c] = Wr[i];
    }
    __syncthreads();
    int n = blockIdx.x * 256 + tid;
    if (n >= N_NODES) return;
    float accA[10], accB[10];
#pragma unroll
    for (int c = 0; c < 10; c++) { accA[c] = 0.f; accB[c] = 0.f; }
    const float4* X4 = (const float4*)X;
#pragma unroll 4
    for (int k4 = 0; k4 < 32; k4++) {
        float4 h = X4[n * 32 + k4];
        float hv[4] = {h.x, h.y, h.z, h.w};
#pragma unroll
        for (int j = 0; j < 4; j++) {
            const float* w = &sW[(k4 * 4 + j) * 20];
#pragma unroll
            for (int c = 0; c < 10; c++) {
                accA[c] += hv[j] * w[c];
                accB[c] += hv[j] * w[10 + c];
            }
        }
    }
#pragma unroll
    for (int c = 0; c < 10; c++) {
        A[n * 10 + c] = accA[c];
        B[n * 10 + c] = accB[c];
    }
}

// -------- layer-3 gather + finalize + graph pool (16 threads/node) --------
__global__ __launch_bounds__(256) void gather10_pool(
    const float* __restrict__ A3, const float* __restrict__ B3,
    const float* __restrict__ bl3, const int* __restrict__ batch) {
    int gid = blockIdx.x * blockDim.x + threadIdx.x;
    int node = gid >> 4;
    int lane = gid & 15;
    if (node >= N_NODES || lane >= N_CLASSES) return;
    const int beg = g_off[node];
    const int end = g_off[node + 1];
    float acc = 0.f;
    for (int j = beg; j < end; j++)
        acc += A3[g_csr_src[j] * N_CLASSES + lane];
    int deg = end - beg;
    float inv = 1.0f / (float)(deg > 1 ? deg : 1);
    float h = acc * inv + B3[node * N_CLASSES + lane] + bl3[lane];
    atomicAdd(&g_pool[batch[node] * N_CLASSES + lane], h);
}

// -------- pooled mean + log_softmax --------
__global__ void final_out_kernel(float* __restrict__ out) {
    int g = threadIdx.x;
    if (g >= N_GRAPHS) return;
    float cnt = g_gcnt[g];
    float inv = 1.0f / (cnt > 1.0f ? cnt : 1.0f);
    float v[N_CLASSES];
    float mx = -1e30f;
#pragma unroll
    for (int c = 0; c < N_CLASSES; c++) {
        v[c] = g_pool[g * N_CLASSES + c] * inv;
        mx = v[c] > mx ? v[c] : mx;
    }
    float s = 0.f;
#pragma unroll
    for (int c = 0; c < N_CLASSES; c++) s += expf(v[c] - mx);
    float ls = logf(s);
#pragma unroll
    for (int c = 0; c < N_CLASSES; c++) out[g * N_CLASSES + c] = v[c] - mx - ls;
}

// -------- host launch --------
extern "C" void kernel_launch(void* const* d_in, const int* in_sizes, int n_in,
                              void* d_out, int out_size) {
    const float* x = (const float*)d_in[0];
    const int* ei = (const int*)d_in[1];
    const int* batch = (const int*)d_in[2];
    const float* Wl1 = (const float*)d_in[3];
    const float* bl1 = (const float*)d_in[4];
    const float* Wr1 = (const float*)d_in[5];
    const float* Wl2 = (const float*)d_in[6];
    const float* bl2 = (const float*)d_in[7];
    const float* Wr2 = (const float*)d_in[8];
    const float* Wl3 = (const float*)d_in[9];
    const float* bl3 = (const float*)d_in[10];
    const float* Wr3 = (const float*)d_in[11];
    float* out = (float*)d_out;

    float *A, *B, *H, *A3, *B3;
    cudaGetSymbolAddress((void**)&A, g_A);
    cudaGetSymbolAddress((void**)&B, g_B);
    cudaGetSymbolAddress((void**)&H, g_H);
    cudaGetSymbolAddress((void**)&A3, g_A3);
    cudaGetSymbolAddress((void**)&B3, g_B3);

    const int SMEM_BF = 6 * 128 * TW * 4;  // 208896 B
    cudaFuncSetAttribute(gemm_dual128_bf16, cudaFuncAttributeMaxDynamicSharedMemorySize,
                         SMEM_BF);

    const int gemm_grid = (N_NODES + 127) / 128;  // 391
    const int warp_grid = (N_NODES * 32 + 255) / 256;

    // ---- CSR build + counts ----
    zero_misc_kernel<<<(N_NODES + 255) / 256, 256>>>();
    count_kernel<<<(N_EDGES + 255) / 256, 256>>>(ei, batch);
    scan1_kernel<<<SCAN_BLOCKS, 256>>>();
    scan2_kernel<<<1, 256>>>();
    scan3_kernel<<<SCAN_BLOCKS, 256>>>();
    fill_csr_kernel<<<(N_EDGES + 255) / 256, 256>>>(ei);

    // ---- layer 1 ----
    gemm_dual128_bf16<<<gemm_grid, 256, SMEM_BF>>>(x, Wl1, Wr1, A, B);
    gather_fin128<<<warp_grid, 256>>>(A, B, bl1, H);

    // ---- layer 2 ----
    gemm_dual128_bf16<<<gemm_grid, 256, SMEM_BF>>>(H, Wl2, Wr2, A, B);
    gather_fin128<<<warp_grid, 256>>>(A, B, bl2, H);

    // ---- layer 3 (aggregate post-GEMM: 10-dim) ----
    gemm_dual10<<<(N_NODES + 255) / 256, 256>>>(H, Wl3, Wr3, A3, B3);
    gather10_pool<<<(N_NODES * 16 + 255) / 256, 256>>>(A3, B3, bl3, batch);

    final_out_kernel<<<1, 256>>>(out);
}

// round 8
// speedup vs baseline: 12.7437x; 1.0307x over previous
#include <cuda_runtime.h>
#include <cuda_bf16.h>
#include <cstdint>

#define N_NODES 50000
#define N_EDGES 800000
#define F_IN 128
#define HIDDEN 128
#define N_CLASSES 10
#define N_GRAPHS 256
#define SCAN_BLOCKS 196  // ceil(50000/256)

#define TW 68  // words (bf16x2) per row in smem tiles: 64 data + 4 pad

// -------- scratch (static device globals) --------
__device__ int g_degi[N_NODES];
__device__ int g_off[N_NODES + 1];
__device__ int g_cur[N_NODES];
__device__ int g_bsum[256];
__device__ int g_csr_src[N_EDGES];
__device__ float g_gcnt[N_GRAPHS];
__device__ float g_pool[N_GRAPHS * N_CLASSES];
__device__ __align__(16) float g_A[N_NODES * HIDDEN];
__device__ __align__(16) float g_B[N_NODES * HIDDEN];
__device__ __align__(16) float g_H[N_NODES * HIDDEN];
__device__ float g_A3[N_NODES * N_CLASSES];
__device__ float g_B3[N_NODES * N_CLASSES];

// -------- zero + fused counts --------
__global__ void zero_misc_kernel() {
    int i = blockIdx.x * blockDim.x + threadIdx.x;
    if (i < N_NODES) g_degi[i] = 0;
    if (i < N_GRAPHS) g_gcnt[i] = 0.f;
    if (i < N_GRAPHS * N_CLASSES) g_pool[i] = 0.f;
}

__global__ void count_kernel(const int* __restrict__ ei, const int* __restrict__ batch) {
    int e = blockIdx.x * blockDim.x + threadIdx.x;
    if (e < N_EDGES) atomicAdd(&g_degi[ei[N_EDGES + e]], 1);
    if (e < N_NODES) atomicAdd(&g_gcnt[batch[e]], 1.0f);
}

// -------- 3-phase parallel exclusive scan over degrees --------
__global__ __launch_bounds__(256) void scan1_kernel() {
    __shared__ int ws[8];
    const int t = threadIdx.x;
    const int lane = t & 31;
    const int warp = t >> 5;
    const int i = blockIdx.x * 256 + t;
    int v = (i < N_NODES) ? g_degi[i] : 0;
    int x = v;
#pragma unroll
    for (int off = 1; off < 32; off <<= 1) {
        int y = __shfl_up_sync(0xFFFFFFFFu, x, off);
        if (lane >= off) x += y;
    }
    if (lane == 31) ws[warp] = x;
    __syncthreads();
    if (warp == 0 && lane < 8) {
        int s = ws[lane];
#pragma unroll
        for (int off = 1; off < 8; off <<= 1) {
            int y = __shfl_up_sync(0xFFu, s, off);
            if (lane >= off) s += y;
        }
        ws[lane] = s;
    }
    __syncthreads();
    int incl = x + (warp > 0 ? ws[warp - 1] : 0);
    if (i < N_NODES) g_off[i] = incl - v;
    if (t == 255) g_bsum[blockIdx.x] = incl;
}

__global__ __launch_bounds__(256) void scan2_kernel() {
    __shared__ int ws[8];
    const int t = threadIdx.x;
    const int lane = t & 31;
    const int warp = t >> 5;
    int v = (t < SCAN_BLOCKS) ? g_bsum[t] : 0;
    int x = v;
#pragma unroll
    for (int off = 1; off < 32; off <<= 1) {
        int y = __shfl_up_sync(0xFFFFFFFFu, x, off);
        if (lane >= off) x += y;
    }
    if (lane == 31) ws[warp] = x;
    __syncthreads();
    if (warp == 0 && lane < 8) {
        int s = ws[lane];
#pragma unroll
        for (int off = 1; off < 8; off <<= 1) {
            int y = __shfl_up_sync(0xFFu, s, off);
            if (lane >= off) s += y;
        }
        ws[lane] = s;
    }
    __syncthreads();
    int incl = x + (warp > 0 ? ws[warp - 1] : 0);
    g_bsum[t] = incl - v;
}

__global__ void scan3_kernel() {
    int i = blockIdx.x * blockDim.x + threadIdx.x;
    if (i < N_NODES) {
        int o = g_off[i] + g_bsum[i >> 8];
        g_off[i] = o;
        g_cur[i] = o;
    }
    if (i == 0) g_off[N_NODES] = N_EDGES;
}

__global__ void fill_csr_kernel(const int* __restrict__ ei) {
    int e = blockIdx.x * blockDim.x + threadIdx.x;
    if (e >= N_EDGES) return;
    int src = ei[e];
    int dst = ei[N_EDGES + e];
    int slot = atomicAdd(&g_cur[dst], 1);
    g_csr_src[slot] = src;
}

// ======== bf16 mma.sync dual GEMM (3-term compensated) ========
__device__ __forceinline__ uint32_t pack_hi(float a, float b) {
    __nv_bfloat162 h = __floats2bfloat162_rn(a, b);
    return *(uint32_t*)&h;
}
__device__ __forceinline__ uint32_t pack_lo(float a, float b, uint32_t hi) {
    __nv_bfloat162 h = *(__nv_bfloat162*)&hi;
    __nv_bfloat162 l =
        __floats2bfloat162_rn(a - __bfloat162float(h.x), b - __bfloat162float(h.y));
    return *(uint32_t*)&l;
}
__device__ __forceinline__ void mma_bf16(float* d, const uint32_t* a, uint32_t b0,
                                         uint32_t b1) {
    asm volatile(
        "mma.sync.aligned.m16n8k16.row.col.f32.bf16.bf16.f32 "
        "{%0,%1,%2,%3}, {%4,%5,%6,%7}, {%8,%9}, {%0,%1,%2,%3};"
        : "+f"(d[0]), "+f"(d[1]), "+f"(d[2]), "+f"(d[3])
        : "r"(a[0]), "r"(a[1]), "r"(a[2]), "r"(a[3]), "r"(b0), "r"(b1));
}

// One CTA: 128 rows x (Wl 128 cols + Wr 128 cols), K=128. 256 threads, 204KB smem.
__global__ __launch_bounds__(256) void gemm_dual128_bf16(
    const float* __restrict__ X, const float* __restrict__ Wl,
    const float* __restrict__ Wr, float* __restrict__ A, float* __restrict__ B) {
    extern __shared__ uint32_t smw[];
    uint32_t* Xhi = smw;
    uint32_t* Xlo = smw + 128 * TW;
    uint32_t* Wtiles[4] = {smw + 2 * 128 * TW, smw + 3 * 128 * TW,
                           smw + 4 * 128 * TW, smw + 5 * 128 * TW};  // hiL, loL, hiR, loR
    const int tid = threadIdx.x;
    const int row0 = blockIdx.x * 128;

    // ---- stage X -> Xhi/Xlo (packed bf16x2 along k) ----
    const float4* X4 = (const float4*)X;
    for (int i = tid; i < 128 * 32; i += 256) {
        int r = i >> 5, c4 = i & 31;
        int gr = row0 + r;
        float4 v = (gr < N_NODES) ? X4[gr * 32 + c4] : make_float4(0.f, 0.f, 0.f, 0.f);
        uint32_t h0 = pack_hi(v.x, v.y), h1 = pack_hi(v.z, v.w);
        Xhi[r * TW + 2 * c4] = h0;
        Xhi[r * TW + 2 * c4 + 1] = h1;
        Xlo[r * TW + 2 * c4] = pack_lo(v.x, v.y, h0);
        Xlo[r * TW + 2 * c4 + 1] = pack_lo(v.z, v.w, h1);
    }
    // ---- stage W -> [n][k] transposed hi/lo ----
    for (int i = tid; i < 128 * 64; i += 256) {
        int n = i & 127, j = i >> 7;  // j = k-pair index
        float l0 = Wl[(2 * j) * 128 + n], l1 = Wl[(2 * j + 1) * 128 + n];
        float r0 = Wr[(2 * j) * 128 + n], r1 = Wr[(2 * j + 1) * 128 + n];
        uint32_t hl = pack_hi(l0, l1), hr = pack_hi(r0, r1);
        Wtiles[0][n * TW + j] = hl;
        Wtiles[1][n * TW + j] = pack_lo(l0, l1, hl);
        Wtiles[2][n * TW + j] = hr;
        Wtiles[3][n * TW + j] = pack_lo(r0, r1, hr);
    }
    __syncthreads();

    const int warp = tid >> 5, lane = tid & 31;
    const int mw = warp >> 1;  // 0..3: rows mw*32
    const int nw = warp & 1;   // 0..1: cols nw*64 (within 128-col phase)
    const int g = lane >> 2, tg = lane & 3;

    for (int phase = 0; phase < 2; phase++) {
        const uint32_t* Wh = Wtiles[phase * 2];
        const uint32_t* Wo = Wtiles[phase * 2 + 1];
        float* OUT = phase ? B : A;

        float acc[2][8][4];
#pragma unroll
        for (int mt = 0; mt < 2; mt++)
#pragma unroll
            for (int nt = 0; nt < 8; nt++)
#pragma unroll
                for (int q = 0; q < 4; q++) acc[mt][nt][q] = 0.f;

#pragma unroll
        for (int ks = 0; ks < 8; ks++) {  // k16 steps
            const int j0 = ks * 8;
            uint32_t ahi[2][4], alo[2][4];
#pragma unroll
            for (int mt = 0; mt < 2; mt++) {
                int rb = mw * 32 + mt * 16;
                ahi[mt][0] = Xhi[(rb + g) * TW + j0 + tg];
                ahi[mt][1] = Xhi[(rb + 8 + g) * TW + j0 + tg];
                ahi[mt][2] = Xhi[(rb + g) * TW + j0 + 4 + tg];
                ahi[mt][3] = Xhi[(rb + 8 + g) * TW + j0 + 4 + tg];
                alo[mt][0] = Xlo[(rb + g) * TW + j0 + tg];
                alo[mt][1] = Xlo[(rb + 8 + g) * TW + j0 + tg];
                alo[mt][2] = Xlo[(rb + g) * TW + j0 + 4 + tg];
                alo[mt][3] = Xlo[(rb + 8 + g) * TW + j0 + 4 + tg];
            }
#pragma unroll
            for (int nt = 0; nt < 8; nt++) {
                int col = nw * 64 + nt * 8 + g;
                uint32_t bh0 = Wh[col * TW + j0 + tg];
                uint32_t bh1 = Wh[col * TW + j0 + 4 + tg];
                uint32_t bl0 = Wo[col * TW + j0 + tg];
                uint32_t bl1 = Wo[col * TW + j0 + 4 + tg];
#pragma unroll
                for (int mt = 0; mt < 2; mt++) {
                    mma_bf16(acc[mt][nt], ahi[mt], bh0, bh1);
                    mma_bf16(acc[mt][nt], alo[mt], bh0, bh1);
                    mma_bf16(acc[mt][nt], ahi[mt], bl0, bl1);
                }
            }
        }

        // epilogue: c0,c1 -> row g, cols 2tg,2tg+1; c2,c3 -> row g+8
#pragma unroll
        for (int mt = 0; mt < 2; mt++) {
            int gr0 = row0 + mw * 32 + mt * 16 + g;
            int gr1 = gr0 + 8;
#pragma unroll
            for (int nt = 0; nt < 8; nt++) {
                int gc = nw * 64 + nt * 8 + tg * 2;
                if (gr0 < N_NODES)
                    *(float2*)&OUT[gr0 * 128 + gc] =
                        make_float2(acc[mt][nt][0], acc[mt][nt][1]);
                if (gr1 < N_NODES)
                    *(float2*)&OUT[gr1 * 128 + gc] =
                        make_float2(acc[mt][nt][2], acc[mt][nt][3]);
            }
        }
    }
}

// -------- CSR gather + finalize: H = mean A[src] + B + bias --------
__global__ __launch_bounds__(256) void gather_fin128(
    const float* __restrict__ A, const float* __restrict__ B,
    const float* __restrict__ bias, float* __restrict__ H) {
    int warp = (blockIdx.x * blockDim.x + threadIdx.x) >> 5;
    int lane = threadIdx.x & 31;
    if (warp >= N_NODES) return;
    const int beg = g_off[warp];
    const int end = g_off[warp + 1];
    const float4* A4 = (const float4*)A;
    float4 acc = make_float4(0.f, 0.f, 0.f, 0.f);
    int j = beg;
    for (; j + 3 < end; j += 4) {
        int s0 = g_csr_src[j];
        int s1 = g_csr_src[j + 1];
        int s2 = g_csr_src[j + 2];
        int s3 = g_csr_src[j + 3];
        float4 v0 = A4[s0 * 32 + lane];
        float4 v1 = A4[s1 * 32 + lane];
        float4 v2 = A4[s2 * 32 + lane];
        float4 v3 = A4[s3 * 32 + lane];
        acc.x += (v0.x + v1.x) + (v2.x + v3.x);
        acc.y += (v0.y + v1.y) + (v2.y + v3.y);
        acc.z += (v0.z + v1.z) + (v2.z + v3.z);
        acc.w += (v0.w + v1.w) + (v2.w + v3.w);
    }
    for (; j < end; j++) {
        float4 v = A4[g_csr_src[j] * 32 + lane];
        acc.x += v.x; acc.y += v.y; acc.z += v.z; acc.w += v.w;
    }
    int deg = end - beg;
    float inv = 1.0f / (float)(deg > 1 ? deg : 1);
    float4 b = ((const float4*)B)[warp * 32 + lane];
    float4 bi = ((const float4*)bias)[lane];
    float4 h;
    h.x = acc.x * inv + b.x + bi.x;
    h.y = acc.y * inv + b.y + bi.y;
    h.z = acc.z * inv + b.z + bi.z;
    h.w = acc.w * inv + b.w + bi.w;
    ((float4*)H)[warp * 32 + lane] = h;
}

// -------- layer-3 dual GEMM: thread per node, weights in smem --------
__global__ __launch_bounds__(256) void gemm_dual10(
    const float* __restrict__ X, const float* __restrict__ Wl,
    const float* __restrict__ Wr, float* __restrict__ A, float* __restrict__ B) {
    __shared__ float sW[128 * 20];
    const int tid = threadIdx.x;
    for (int i = tid; i < 128 * 10; i += 256) {
        int k = i / 10;
        int c = i - k * 10;
        sW[k * 20 + c] = Wl[i];
        sW[k * 20 + 10 + c] = Wr[i];
    }
    __syncthreads();
    int n = blockIdx.x * 256 + tid;
    if (n >= N_NODES) return;
    float accA[10], accB[10];
#pragma unroll
    for (int c = 0; c < 10; c++) { accA[c] = 0.f; accB[c] = 0.f; }
    const float4* X4 = (const float4*)X;
#pragma unroll 4
    for (int k4 = 0; k4 < 32; k4++) {
        float4 h = X4[n * 32 + k4];
        float hv[4] = {h.x, h.y, h.z, h.w};
#pragma unroll
        for (int j = 0; j < 4; j++) {
            const float* w = &sW[(k4 * 4 + j) * 20];
#pragma unroll
            for (int c = 0; c < 10; c++) {
                accA[c] += hv[j] * w[c];
                accB[c] += hv[j] * w[10 + c];
            }
        }
    }
#pragma unroll
    for (int c = 0; c < 10; c++) {
        A[n * 10 + c] = accA[c];
        B[n * 10 + c] = accB[c];
    }
}

// -------- layer-3 gather + finalize + graph pool (16 threads/node) --------
__global__ __launch_bounds__(256) void gather10_pool(
    const float* __restrict__ A3, const float* __restrict__ B3,
    const float* __restrict__ bl3, const int* __restrict__ batch) {
    int gid = blockIdx.x * blockDim.x + threadIdx.x;
    int node = gid >> 4;
    int lane = gid & 15;
    if (node >= N_NODES || lane >= N_CLASSES) return;
    const int beg = g_off[node];
    const int end = g_off[node + 1];
    float acc = 0.f;
    for (int j = beg; j < end; j++)
        acc += A3[g_csr_src[j] * N_CLASSES + lane];
    int deg = end - beg;
    float inv = 1.0f / (float)(deg > 1 ? deg : 1);
    float h = acc * inv + B3[node * N_CLASSES + lane] + bl3[lane];
    atomicAdd(&g_pool[batch[node] * N_CLASSES + lane], h);
}

// -------- pooled mean + log_softmax --------
__global__ void final_out_kernel(float* __restrict__ out) {
    int g = threadIdx.x;
    if (g >= N_GRAPHS) return;
    float cnt = g_gcnt[g];
    float inv = 1.0f / (cnt > 1.0f ? cnt : 1.0f);
    float v[N_CLASSES];
    float mx = -1e30f;
#pragma unroll
    for (int c = 0; c < N_CLASSES; c++) {
        v[c] = g_pool[g * N_CLASSES + c] * inv;
        mx = v[c] > mx ? v[c] : mx;
    }
    float s = 0.f;
#pragma unroll
    for (int c = 0; c < N_CLASSES; c++) s += expf(v[c] - mx);
    float ls = logf(s);
#pragma unroll
    for (int c = 0; c < N_CLASSES; c++) out[g * N_CLASSES + c] = v[c] - mx - ls;
}

// -------- host launch --------
extern "C" void kernel_launch(void* const* d_in, const int* in_sizes, int n_in,
                              void* d_out, int out_size) {
    const float* x = (const float*)d_in[0];
    const int* ei = (const int*)d_in[1];
    const int* batch = (const int*)d_in[2];
    const float* Wl1 = (const float*)d_in[3];
    const float* bl1 = (const float*)d_in[4];
    const float* Wr1 = (const float*)d_in[5];
    const float* Wl2 = (const float*)d_in[6];
    const float* bl2 = (const float*)d_in[7];
    const float* Wr2 = (const float*)d_in[8];
    const float* Wl3 = (const float*)d_in[9];
    const float* bl3 = (const float*)d_in[10];
    const float* Wr3 = (const float*)d_in[11];
    float* out = (float*)d_out;

    float *A, *B, *H, *A3, *B3;
    cudaGetSymbolAddress((void**)&A, g_A);
    cudaGetSymbolAddress((void**)&B, g_B);
    cudaGetSymbolAddress((void**)&H, g_H);
    cudaGetSymbolAddress((void**)&A3, g_A3);
    cudaGetSymbolAddress((void**)&B3, g_B3);

    const int SMEM_BF = 6 * 128 * TW * 4;  // 208896 B
    cudaFuncSetAttribute(gemm_dual128_bf16, cudaFuncAttributeMaxDynamicSharedMemorySize,
                         SMEM_BF);

    // one-time side stream + events (created on the un-captured correctness call)
    static cudaStream_t s1 = nullptr;
    static cudaEvent_t evFork = nullptr, evJoin = nullptr;
    if (s1 == nullptr) {
        cudaStreamCreateWithFlags(&s1, cudaStreamNonBlocking);
        cudaEventCreateWithFlags(&evFork, cudaEventDisableTiming);
        cudaEventCreateWithFlags(&evJoin, cudaEventDisableTiming);
    }

    const int gemm_grid = (N_NODES + 127) / 128;  // 391
    const int warp_grid = (N_NODES * 32 + 255) / 256;

    // ---- fork: CSR build chain on side stream (independent of layer-1 GEMM) ----
    cudaEventRecord(evFork, 0);
    cudaStreamWaitEvent(s1, evFork, 0);
    zero_misc_kernel<<<(N_NODES + 255) / 256, 256, 0, s1>>>();
    count_kernel<<<(N_EDGES + 255) / 256, 256, 0, s1>>>(ei, batch);
    scan1_kernel<<<SCAN_BLOCKS, 256, 0, s1>>>();
    scan2_kernel<<<1, 256, 0, s1>>>();
    scan3_kernel<<<SCAN_BLOCKS, 256, 0, s1>>>();
    fill_csr_kernel<<<(N_EDGES + 255) / 256, 256, 0, s1>>>(ei);
    cudaEventRecord(evJoin, s1);

    // ---- layer-1 GEMM concurrently on main stream ----
    gemm_dual128_bf16<<<gemm_grid, 256, SMEM_BF>>>(x, Wl1, Wr1, A, B);

    // ---- join: gather needs CSR + A ----
    cudaStreamWaitEvent(0, evJoin, 0);
    gather_fin128<<<warp_grid, 256>>>(A, B, bl1, H);

    // ---- layer 2 ----
    gemm_dual128_bf16<<<gemm_grid, 256, SMEM_BF>>>(H, Wl2, Wr2, A, B);
    gather_fin128<<<warp_grid, 256>>>(A, B, bl2, H);

    // ---- layer 3 (aggregate post-GEMM: 10-dim) ----
    gemm_dual10<<<(N_NODES + 255) / 256, 256>>>(H, Wl3, Wr3, A3, B3);
    gather10_pool<<<(N_NODES * 16 + 255) / 256, 256>>>(A3, B3, bl3, batch);

    final_out_kernel<<<1, 256>>>(out);
}

// round 9
// speedup vs baseline: 13.7273x; 1.0772x over previous
#include <cuda_runtime.h>
#include <cuda_bf16.h>
#include <cuda_fp16.h>
#include <cstdint>

#define N_NODES 50000
#define N_EDGES 800000
#define F_IN 128
#define HIDDEN 128
#define N_CLASSES 10
#define N_GRAPHS 256
#define SCAN_BLOCKS 196  // ceil(50000/256)

#define TW 68  // words (bf16x2) per row in smem tiles: 64 data + 4 pad

// -------- scratch (static device globals) --------
__device__ int g_degi[N_NODES];
__device__ int g_off[N_NODES + 1];
__device__ int g_cur[N_NODES];
__device__ int g_bsum[256];
__device__ int g_csr_src[N_EDGES];
__device__ float g_gcnt[N_GRAPHS];
__device__ float g_pool[N_GRAPHS * N_CLASSES];
__device__ __align__(16) __half g_Ah[N_NODES * HIDDEN];  // fp16 message matrix
__device__ __align__(16) float g_B[N_NODES * HIDDEN];
__device__ __align__(16) float g_H[N_NODES * HIDDEN];
__device__ float g_A3[N_NODES * N_CLASSES];
__device__ float g_B3[N_NODES * N_CLASSES];

// -------- zero + fused counts --------
__global__ void zero_misc_kernel() {
    int i = blockIdx.x * blockDim.x + threadIdx.x;
    if (i < N_NODES) g_degi[i] = 0;
    if (i < N_GRAPHS) g_gcnt[i] = 0.f;
    if (i < N_GRAPHS * N_CLASSES) g_pool[i] = 0.f;
}

__global__ void count_kernel(const int* __restrict__ ei, const int* __restrict__ batch) {
    int e = blockIdx.x * blockDim.x + threadIdx.x;
    if (e < N_EDGES) atomicAdd(&g_degi[ei[N_EDGES + e]], 1);
    if (e < N_NODES) atomicAdd(&g_gcnt[batch[e]], 1.0f);
}

// -------- 3-phase parallel exclusive scan over degrees --------
__global__ __launch_bounds__(256) void scan1_kernel() {
    __shared__ int ws[8];
    const int t = threadIdx.x;
    const int lane = t & 31;
    const int warp = t >> 5;
    const int i = blockIdx.x * 256 + t;
    int v = (i < N_NODES) ? g_degi[i] : 0;
    int x = v;
#pragma unroll
    for (int off = 1; off < 32; off <<= 1) {
        int y = __shfl_up_sync(0xFFFFFFFFu, x, off);
        if (lane >= off) x += y;
    }
    if (lane == 31) ws[warp] = x;
    __syncthreads();
    if (warp == 0 && lane < 8) {
        int s = ws[lane];
#pragma unroll
        for (int off = 1; off < 8; off <<= 1) {
            int y = __shfl_up_sync(0xFFu, s, off);
            if (lane >= off) s += y;
        }
        ws[lane] = s;
    }
    __syncthreads();
    int incl = x + (warp > 0 ? ws[warp - 1] : 0);
    if (i < N_NODES) g_off[i] = incl - v;
    if (t == 255) g_bsum[blockIdx.x] = incl;
}

__global__ __launch_bounds__(256) void scan2_kernel() {
    __shared__ int ws[8];
    const int t = threadIdx.x;
    const int lane = t & 31;
    const int warp = t >> 5;
    int v = (t < SCAN_BLOCKS) ? g_bsum[t] : 0;
    int x = v;
#pragma unroll
    for (int off = 1; off < 32; off <<= 1) {
        int y = __shfl_up_sync(0xFFFFFFFFu, x, off);
        if (lane >= off) x += y;
    }
    if (lane == 31) ws[warp] = x;
    __syncthreads();
    if (warp == 0 && lane < 8) {
        int s = ws[lane];
#pragma unroll
        for (int off = 1; off < 8; off <<= 1) {
            int y = __shfl_up_sync(0xFFu, s, off);
            if (lane >= off) s += y;
        }
        ws[lane] = s;
    }
    __syncthreads();
    int incl = x + (warp > 0 ? ws[warp - 1] : 0);
    g_bsum[t] = incl - v;
}

__global__ void scan3_kernel() {
    int i = blockIdx.x * blockDim.x + threadIdx.x;
    if (i < N_NODES) {
        int o = g_off[i] + g_bsum[i >> 8];
        g_off[i] = o;
        g_cur[i] = o;
    }
    if (i == 0) g_off[N_NODES] = N_EDGES;
}

__global__ void fill_csr_kernel(const int* __restrict__ ei) {
    int e = blockIdx.x * blockDim.x + threadIdx.x;
    if (e >= N_EDGES) return;
    int src = ei[e];
    int dst = ei[N_EDGES + e];
    int slot = atomicAdd(&g_cur[dst], 1);
    g_csr_src[slot] = src;
}

// ======== bf16 mma.sync dual GEMM (3-term compensated) ========
__device__ __forceinline__ uint32_t pack_hi(float a, float b) {
    __nv_bfloat162 h = __floats2bfloat162_rn(a, b);
    return *(uint32_t*)&h;
}
__device__ __forceinline__ uint32_t pack_lo(float a, float b, uint32_t hi) {
    __nv_bfloat162 h = *(__nv_bfloat162*)&hi;
    __nv_bfloat162 l =
        __floats2bfloat162_rn(a - __bfloat162float(h.x), b - __bfloat162float(h.y));
    return *(uint32_t*)&l;
}
__device__ __forceinline__ void mma_bf16(float* d, const uint32_t* a, uint32_t b0,
                                         uint32_t b1) {
    asm volatile(
        "mma.sync.aligned.m16n8k16.row.col.f32.bf16.bf16.f32 "
        "{%0,%1,%2,%3}, {%4,%5,%6,%7}, {%8,%9}, {%0,%1,%2,%3};"
        : "+f"(d[0]), "+f"(d[1]), "+f"(d[2]), "+f"(d[3])
        : "r"(a[0]), "r"(a[1]), "r"(a[2]), "r"(a[3]), "r"(b0), "r"(b1));
}

// One CTA: 128 rows x (Wl -> fp16 A, Wr -> fp32 B), K=128. 256 threads, 204KB smem.
__global__ __launch_bounds__(256) void gemm_dual128_bf16(
    const float* __restrict__ X, const float* __restrict__ Wl,
    const float* __restrict__ Wr, __half* __restrict__ Ah, float* __restrict__ B) {
    extern __shared__ uint32_t smw[];
    uint32_t* Xhi = smw;
    uint32_t* Xlo = smw + 128 * TW;
    uint32_t* Wtiles[4] = {smw + 2 * 128 * TW, smw + 3 * 128 * TW,
                           smw + 4 * 128 * TW, smw + 5 * 128 * TW};  // hiL, loL, hiR, loR
    const int tid = threadIdx.x;
    const int row0 = blockIdx.x * 128;

    // ---- stage X -> Xhi/Xlo (packed bf16x2 along k) ----
    const float4* X4 = (const float4*)X;
    for (int i = tid; i < 128 * 32; i += 256) {
        int r = i >> 5, c4 = i & 31;
        int gr = row0 + r;
        float4 v = (gr < N_NODES) ? X4[gr * 32 + c4] : make_float4(0.f, 0.f, 0.f, 0.f);
        uint32_t h0 = pack_hi(v.x, v.y), h1 = pack_hi(v.z, v.w);
        Xhi[r * TW + 2 * c4] = h0;
        Xhi[r * TW + 2 * c4 + 1] = h1;
        Xlo[r * TW + 2 * c4] = pack_lo(v.x, v.y, h0);
        Xlo[r * TW + 2 * c4 + 1] = pack_lo(v.z, v.w, h1);
    }
    // ---- stage W -> [n][k] transposed hi/lo ----
    for (int i = tid; i < 128 * 64; i += 256) {
        int n = i & 127, j = i >> 7;  // j = k-pair index
        float l0 = Wl[(2 * j) * 128 + n], l1 = Wl[(2 * j + 1) * 128 + n];
        float r0 = Wr[(2 * j) * 128 + n], r1 = Wr[(2 * j + 1) * 128 + n];
        uint32_t hl = pack_hi(l0, l1), hr = pack_hi(r0, r1);
        Wtiles[0][n * TW + j] = hl;
        Wtiles[1][n * TW + j] = pack_lo(l0, l1, hl);
        Wtiles[2][n * TW + j] = hr;
        Wtiles[3][n * TW + j] = pack_lo(r0, r1, hr);
    }
    __syncthreads();

    const int warp = tid >> 5, lane = tid & 31;
    const int mw = warp >> 1;  // 0..3: rows mw*32
    const int nw = warp & 1;   // 0..1: cols nw*64 (within 128-col phase)
    const int g = lane >> 2, tg = lane & 3;
    uint32_t* Ah32 = (uint32_t*)Ah;

    for (int phase = 0; phase < 2; phase++) {
        const uint32_t* Wh = Wtiles[phase * 2];
        const uint32_t* Wo = Wtiles[phase * 2 + 1];

        float acc[2][8][4];
#pragma unroll
        for (int mt = 0; mt < 2; mt++)
#pragma unroll
            for (int nt = 0; nt < 8; nt++)
#pragma unroll
                for (int q = 0; q < 4; q++) acc[mt][nt][q] = 0.f;

#pragma unroll
        for (int ks = 0; ks < 8; ks++) {  // k16 steps
            const int j0 = ks * 8;
            uint32_t ahi[2][4], alo[2][4];
#pragma unroll
            for (int mt = 0; mt < 2; mt++) {
                int rb = mw * 32 + mt * 16;
                ahi[mt][0] = Xhi[(rb + g) * TW + j0 + tg];
                ahi[mt][1] = Xhi[(rb + 8 + g) * TW + j0 + tg];
                ahi[mt][2] = Xhi[(rb + g) * TW + j0 + 4 + tg];
                ahi[mt][3] = Xhi[(rb + 8 + g) * TW + j0 + 4 + tg];
                alo[mt][0] = Xlo[(rb + g) * TW + j0 + tg];
                alo[mt][1] = Xlo[(rb + 8 + g) * TW + j0 + tg];
                alo[mt][2] = Xlo[(rb + g) * TW + j0 + 4 + tg];
                alo[mt][3] = Xlo[(rb + 8 + g) * TW + j0 + 4 + tg];
            }
#pragma unroll
            for (int nt = 0; nt < 8; nt++) {
                int col = nw * 64 + nt * 8 + g;
                uint32_t bh0 = Wh[col * TW + j0 + tg];
                uint32_t bh1 = Wh[col * TW + j0 + 4 + tg];
                uint32_t bl0 = Wo[col * TW + j0 + tg];
                uint32_t bl1 = Wo[col * TW + j0 + 4 + tg];
#pragma unroll
                for (int mt = 0; mt < 2; mt++) {
                    mma_bf16(acc[mt][nt], ahi[mt], bh0, bh1);
                    mma_bf16(acc[mt][nt], alo[mt], bh0, bh1);
                    mma_bf16(acc[mt][nt], ahi[mt], bl0, bl1);
                }
            }
        }

        // epilogue: c0,c1 -> row g, cols 2tg,2tg+1; c2,c3 -> row g+8
#pragma unroll
        for (int mt = 0; mt < 2; mt++) {
            int gr0 = row0 + mw * 32 + mt * 16 + g;
            int gr1 = gr0 + 8;
#pragma unroll
            for (int nt = 0; nt < 8; nt++) {
                int gc = nw * 64 + nt * 8 + tg * 2;
                if (phase == 0) {  // A -> fp16 packed
                    if (gr0 < N_NODES) {
                        __half2 p = __floats2half2_rn(acc[mt][nt][0], acc[mt][nt][1]);
                        Ah32[gr0 * 64 + (gc >> 1)] = *(uint32_t*)&p;
                    }
                    if (gr1 < N_NODES) {
                        __half2 p = __floats2half2_rn(acc[mt][nt][2], acc[mt][nt][3]);
                        Ah32[gr1 * 64 + (gc >> 1)] = *(uint32_t*)&p;
                    }
                } else {  // B -> fp32
                    if (gr0 < N_NODES)
                        *(float2*)&B[gr0 * 128 + gc] =
                            make_float2(acc[mt][nt][0], acc[mt][nt][1]);
                    if (gr1 < N_NODES)
                        *(float2*)&B[gr1 * 128 + gc] =
                            make_float2(acc[mt][nt][2], acc[mt][nt][3]);
                }
            }
        }
    }
}

// -------- CSR gather + finalize: H = mean Ah[src] + B + bias (fp16 messages) ----
__global__ __launch_bounds__(256) void gather_fin128(
    const __half* __restrict__ Ah, const float* __restrict__ B,
    const float* __restrict__ bias, float* __restrict__ H) {
    int warp = (blockIdx.x * blockDim.x + threadIdx.x) >> 5;
    int lane = threadIdx.x & 31;
    if (warp >= N_NODES) return;
    const int beg = g_off[warp];
    const int end = g_off[warp + 1];
    const uint2* A2 = (const uint2*)Ah;  // 4 halves per uint2; 32 uint2 per row
    float4 acc = make_float4(0.f, 0.f, 0.f, 0.f);
    int j = beg;
    for (; j + 3 < end; j += 4) {
        int s0 = g_csr_src[j];
        int s1 = g_csr_src[j + 1];
        int s2 = g_csr_src[j + 2];
        int s3 = g_csr_src[j + 3];
        uint2 u0 = A2[s0 * 32 + lane];
        uint2 u1 = A2[s1 * 32 + lane];
        uint2 u2 = A2[s2 * 32 + lane];
        uint2 u3 = A2[s3 * 32 + lane];
        float2 a0 = __half22float2(*(__half2*)&u0.x), b0 = __half22float2(*(__half2*)&u0.y);
        float2 a1 = __half22float2(*(__half2*)&u1.x), b1 = __half22float2(*(__half2*)&u1.y);
        float2 a2 = __half22float2(*(__half2*)&u2.x), b2 = __half22float2(*(__half2*)&u2.y);
        float2 a3 = __half22float2(*(__half2*)&u3.x), b3 = __half22float2(*(__half2*)&u3.y);
        acc.x += (a0.x + a1.x) + (a2.x + a3.x);
        acc.y += (a0.y + a1.y) + (a2.y + a3.y);
        acc.z += (b0.x + b1.x) + (b2.x + b3.x);
        acc.w += (b0.y + b1.y) + (b2.y + b3.y);
    }
    for (; j < end; j++) {
        uint2 u = A2[g_csr_src[j] * 32 + lane];
        float2 a = __half22float2(*(__half2*)&u.x), b = __half22float2(*(__half2*)&u.y);
        acc.x += a.x; acc.y += a.y; acc.z += b.x; acc.w += b.y;
    }
    int deg = end - beg;
    float inv = 1.0f / (float)(deg > 1 ? deg : 1);
    float4 b = ((const float4*)B)[warp * 32 + lane];
    float4 bi = ((const float4*)bias)[lane];
    float4 h;
    h.x = acc.x * inv + b.x + bi.x;
    h.y = acc.y * inv + b.y + bi.y;
    h.z = acc.z * inv + b.z + bi.z;
    h.w = acc.w * inv + b.w + bi.w;
    ((float4*)H)[warp * 32 + lane] = h;
}

// -------- layer-3 dual GEMM: thread per node, weights in smem --------
__global__ __launch_bounds__(256) void gemm_dual10(
    const float* __restrict__ X, const float* __restrict__ Wl,
    const float* __restrict__ Wr, float* __restrict__ A, float* __restrict__ B) {
    __shared__ float sW[128 * 20];
    const int tid = threadIdx.x;
    for (int i = tid; i < 128 * 10; i += 256) {
        int k = i / 10;
        int c = i - k * 10;
        sW[k * 20 + c] = Wl[i];
        sW[k * 20 + 10 + c] = Wr[i];
    }
    __syncthreads();
    int n = blockIdx.x * 256 + tid;
    if (n >= N_NODES) return;
    float accA[10], accB[10];
#pragma unroll
    for (int c = 0; c < 10; c++) { accA[c] = 0.f; accB[c] = 0.f; }
    const float4* X4 = (const float4*)X;
#pragma unroll 4
    for (int k4 = 0; k4 < 32; k4++) {
        float4 h = X4[n * 32 + k4];
        float hv[4] = {h.x, h.y, h.z, h.w};
#pragma unroll
        for (int j = 0; j < 4; j++) {
            const float* w = &sW[(k4 * 4 + j) * 20];
#pragma unroll
            for (int c = 0; c < 10; c++) {
                accA[c] += hv[j] * w[c];
                accB[c] += hv[j] * w[10 + c];
            }
        }
    }
#pragma unroll
    for (int c = 0; c < 10; c++) {
        A[n * 10 + c] = accA[c];
        B[n * 10 + c] = accB[c];
    }
}

// -------- layer-3 gather + finalize + graph pool (16 threads/node) --------
__global__ __launch_bounds__(256) void gather10_pool(
    const float* __restrict__ A3, const float* __restrict__ B3,
    const float* __restrict__ bl3, const int* __restrict__ batch) {
    int gid = blockIdx.x * blockDim.x + threadIdx.x;
    int node = gid >> 4;
    int lane = gid & 15;
    if (node >= N_NODES || lane >= N_CLASSES) return;
    const int beg = g_off[node];
    const int end = g_off[node + 1];
    float acc = 0.f;
    for (int j = beg; j < end; j++)
        acc += A3[g_csr_src[j] * N_CLASSES + lane];
    int deg = end - beg;
    float inv = 1.0f / (float)(deg > 1 ? deg : 1);
    float h = acc * inv + B3[node * N_CLASSES + lane] + bl3[lane];
    atomicAdd(&g_pool[batch[node] * N_CLASSES + lane], h);
}

// -------- pooled mean + log_softmax --------
__global__ void final_out_kernel(float* __restrict__ out) {
    int g = threadIdx.x;
    if (g >= N_GRAPHS) return;
    float cnt = g_gcnt[g];
    float inv = 1.0f / (cnt > 1.0f ? cnt : 1.0f);
    float v[N_CLASSES];
    float mx = -1e30f;
#pragma unroll
    for (int c = 0; c < N_CLASSES; c++) {
        v[c] = g_pool[g * N_CLASSES + c] * inv;
        mx = v[c] > mx ? v[c] : mx;
    }
    float s = 0.f;
#pragma unroll
    for (int c = 0; c < N_CLASSES; c++) s += expf(v[c] - mx);
    float ls = logf(s);
#pragma unroll
    for (int c = 0; c < N_CLASSES; c++) out[g * N_CLASSES + c] = v[c] - mx - ls;
}

// -------- host launch --------
extern "C" void kernel_launch(void* const* d_in, const int* in_sizes, int n_in,
                              void* d_out, int out_size) {
    const float* x = (const float*)d_in[0];
    const int* ei = (const int*)d_in[1];
    const int* batch = (const int*)d_in[2];
    const float* Wl1 = (const float*)d_in[3];
    const float* bl1 = (const float*)d_in[4];
    const float* Wr1 = (const float*)d_in[5];
    const float* Wl2 = (const float*)d_in[6];
    const float* bl2 = (const float*)d_in[7];
    const float* Wr2 = (const float*)d_in[8];
    const float* Wl3 = (const float*)d_in[9];
    const float* bl3 = (const float*)d_in[10];
    const float* Wr3 = (const float*)d_in[11];
    float* out = (float*)d_out;

    __half* Ah;
    float *B, *H, *A3, *B3;
    cudaGetSymbolAddress((void**)&Ah, g_Ah);
    cudaGetSymbolAddress((void**)&B, g_B);
    cudaGetSymbolAddress((void**)&H, g_H);
    cudaGetSymbolAddress((void**)&A3, g_A3);
    cudaGetSymbolAddress((void**)&B3, g_B3);

    const int SMEM_BF = 6 * 128 * TW * 4;  // 208896 B
    cudaFuncSetAttribute(gemm_dual128_bf16, cudaFuncAttributeMaxDynamicSharedMemorySize,
                         SMEM_BF);

    // one-time side stream + events (created on the un-captured correctness call)
    static cudaStream_t s1 = nullptr;
    static cudaEvent_t evFork = nullptr, evJoin = nullptr;
    if (s1 == nullptr) {
        cudaStreamCreateWithFlags(&s1, cudaStreamNonBlocking);
        cudaEventCreateWithFlags(&evFork, cudaEventDisableTiming);
        cudaEventCreateWithFlags(&evJoin, cudaEventDisableTiming);
    }

    const int gemm_grid = (N_NODES + 127) / 128;  // 391
    const int warp_grid = (N_NODES * 32 + 255) / 256;

    // ---- fork: CSR build chain on side stream (independent of layer-1 GEMM) ----
    cudaEventRecord(evFork, 0);
    cudaStreamWaitEvent(s1, evFork, 0);
    zero_misc_kernel<<<(N_NODES + 255) / 256, 256, 0, s1>>>();
    count_kernel<<<(N_EDGES + 255) / 256, 256, 0, s1>>>(ei, batch);
    scan1_kernel<<<SCAN_BLOCKS, 256, 0, s1>>>();
    scan2_kernel<<<1, 256, 0, s1>>>();
    scan3_kernel<<<SCAN_BLOCKS, 256, 0, s1>>>();
    fill_csr_kernel<<<(N_EDGES + 255) / 256, 256, 0, s1>>>(ei);
    cudaEventRecord(evJoin, s1);

    // ---- layer-1 GEMM concurrently on main stream ----
    gemm_dual128_bf16<<<gemm_grid, 256, SMEM_BF>>>(x, Wl1, Wr1, Ah, B);

    // ---- join: gather needs CSR + A ----
    cudaStreamWaitEvent(0, evJoin, 0);
    gather_fin128<<<warp_grid, 256>>>(Ah, B, bl1, H);

    // ---- layer 2 ----
    gemm_dual128_bf16<<<gemm_grid, 256, SMEM_BF>>>(H, Wl2, Wr2, Ah, B);
    gather_fin128<<<warp_grid, 256>>>(Ah, B, bl2, H);

    // ---- layer 3 (aggregate post-GEMM: 10-dim) ----
    gemm_dual10<<<(N_NODES + 255) / 256, 256>>>(H, Wl3, Wr3, A3, B3);
    gather10_pool<<<(N_NODES * 16 + 255) / 256, 256>>>(A3, B3, bl3, batch);

    final_out_kernel<<<1, 256>>>(out);
}